// round 1
// baseline (speedup 1.0000x reference)
#include <cuda_runtime.h>
#include <math.h>

// Problem constants
#define BB 2
#define SS 2048
#define EE 1024
#define HH 16
#define HD 64
#define SCALE 0.125f   // 1/sqrt(64)

// Scratch: q,k,v in [B,H,S,HD]; att in [B,S,E]
__device__ float g_q[BB*HH*SS*HD];
__device__ float g_k[BB*HH*SS*HD];
__device__ float g_v[BB*HH*SS*HD];
__device__ float g_att[BB*SS*EE];

// ---------------------------------------------------------------------------
// Kernel 1: fused QKV projection (per-head shared 64x64 weights)
// grid = (B*S / TOK) blocks, 256 threads. Weights + 4 token rows in SMEM.
// ---------------------------------------------------------------------------
#define TOK 4
__global__ void __launch_bounds__(256) qkv_kernel(
    const float* __restrict__ x,
    const float* __restrict__ Wq, const float* __restrict__ bq,
    const float* __restrict__ Wk, const float* __restrict__ bk,
    const float* __restrict__ Wv, const float* __restrict__ bv)
{
    extern __shared__ float sm[];
    float* sW = sm;              // 3 * 4096 floats
    float* sX = sm + 3 * 4096;   // TOK * 1024 floats

    const int tid = threadIdx.x;

    for (int i = tid; i < 4096; i += 256) {
        sW[i]          = Wq[i];
        sW[4096 + i]   = Wk[i];
        sW[8192 + i]   = Wv[i];
    }
    const long base_tok = (long)blockIdx.x * TOK;
    const float* xrow = x + base_tok * EE;
    for (int i = tid; i < TOK * EE; i += 256) sX[i] = xrow[i];
    __syncthreads();

    const int d = tid & 63;                 // output dim (constant per thread)
    const float bqv = bq[d], bkv = bk[d], bvv = bv[d];
    const float* wq = sW + d * 64;
    const float* wk = sW + 4096 + d * 64;
    const float* wv = sW + 8192 + d * 64;

    #pragma unroll
    for (int oh = 0; oh < 4; ++oh) {
        const int h = ((oh * 256 + tid) >> 6);   // head index 0..15
        float aq[TOK], ak[TOK], av[TOK];
        #pragma unroll
        for (int t = 0; t < TOK; ++t) { aq[t] = bqv; ak[t] = bkv; av[t] = bvv; }

        #pragma unroll 8
        for (int k2 = 0; k2 < 64; ++k2) {
            const float wqv = wq[k2], wkv = wk[k2], wvv2 = wv[k2];
            #pragma unroll
            for (int t = 0; t < TOK; ++t) {
                const float xv = sX[t * EE + h * 64 + k2];
                aq[t] = fmaf(wqv, xv, aq[t]);
                ak[t] = fmaf(wkv, xv, ak[t]);
                av[t] = fmaf(wvv2, xv, av[t]);
            }
        }
        #pragma unroll
        for (int t = 0; t < TOK; ++t) {
            const long tok = base_tok + t;
            const int b = (int)(tok >> 11);     // / 2048
            const int s = (int)(tok & 2047);
            const long o = (((long)(b * HH + h) * SS + s) * HD) + d;
            g_q[o] = aq[t];
            g_k[o] = ak[t];
            g_v[o] = av[t];
        }
    }
}

// ---------------------------------------------------------------------------
// Kernel 2: causal flash attention, fp32.
// grid = (S/64, H, B), 256 threads. 64x64 tiles, 4x4 register micro-tiles.
// ---------------------------------------------------------------------------
#define PITCH 65
__global__ void __launch_bounds__(256) attn_kernel()
{
    extern __shared__ float sm[];
    float* sQ = sm;                    // 64 * 65
    float* sK = sQ + 64 * PITCH;
    float* sV = sK + 64 * PITCH;
    float* sP = sV + 64 * PITCH;

    const int tid = threadIdx.x;
    const int qb = blockIdx.x;
    const int h  = blockIdx.y;
    const int b  = blockIdx.z;

    const long head_off = (long)(b * HH + h) * SS * HD;
    const float* Qg = g_q + head_off;
    const float* Kg = g_k + head_off;
    const float* Vg = g_v + head_off;

    const int q0 = qb * 64;

    // Load Q tile (pre-scaled by 1/sqrt(HD))
    for (int i = tid; i < 64 * 16; i += 256) {
        const int r  = i >> 4;
        const int c4 = (i & 15) * 4;
        float4 v = *(const float4*)(Qg + (long)(q0 + r) * HD + c4);
        float* dst = sQ + r * PITCH + c4;
        dst[0] = v.x * SCALE; dst[1] = v.y * SCALE;
        dst[2] = v.z * SCALE; dst[3] = v.w * SCALE;
    }

    const int r0 = (tid >> 4) * 4;   // rows owned by this thread
    const int c0 = (tid & 15) * 4;   // cols / output dims owned

    float m[4], l[4], O[4][4];
    #pragma unroll
    for (int i = 0; i < 4; ++i) {
        m[i] = -INFINITY; l[i] = 0.f;
        #pragma unroll
        for (int j = 0; j < 4; ++j) O[i][j] = 0.f;
    }

    for (int kb = 0; kb <= qb; ++kb) {
        __syncthreads();
        const int k0 = kb * 64;
        // Load K, V tiles
        for (int i = tid; i < 64 * 16; i += 256) {
            const int r  = i >> 4;
            const int c4 = (i & 15) * 4;
            float4 kv = *(const float4*)(Kg + (long)(k0 + r) * HD + c4);
            float4 vv = *(const float4*)(Vg + (long)(k0 + r) * HD + c4);
            float* dk = sK + r * PITCH + c4;
            float* dv = sV + r * PITCH + c4;
            dk[0] = kv.x; dk[1] = kv.y; dk[2] = kv.z; dk[3] = kv.w;
            dv[0] = vv.x; dv[1] = vv.y; dv[2] = vv.z; dv[3] = vv.w;
        }
        __syncthreads();

        // Scores: s = (Q*scale) . K^T
        float s[4][4];
        #pragma unroll
        for (int i = 0; i < 4; ++i)
            #pragma unroll
            for (int j = 0; j < 4; ++j) s[i][j] = 0.f;

        #pragma unroll 8
        for (int d = 0; d < 64; ++d) {
            float qv[4], kv[4];
            #pragma unroll
            for (int i = 0; i < 4; ++i) qv[i] = sQ[(r0 + i) * PITCH + d];
            #pragma unroll
            for (int j = 0; j < 4; ++j) kv[j] = sK[(c0 + j) * PITCH + d];
            #pragma unroll
            for (int i = 0; i < 4; ++i)
                #pragma unroll
                for (int j = 0; j < 4; ++j)
                    s[i][j] = fmaf(qv[i], kv[j], s[i][j]);
        }

        if (kb == qb) {   // diagonal block: causal mask
            #pragma unroll
            for (int i = 0; i < 4; ++i)
                #pragma unroll
                for (int j = 0; j < 4; ++j)
                    if (k0 + c0 + j > q0 + r0 + i) s[i][j] = -1e20f;
        }

        // Online softmax update
        #pragma unroll
        for (int i = 0; i < 4; ++i) {
            float mx = fmaxf(fmaxf(s[i][0], s[i][1]), fmaxf(s[i][2], s[i][3]));
            mx = fmaxf(mx, __shfl_xor_sync(0xffffffffu, mx, 1));
            mx = fmaxf(mx, __shfl_xor_sync(0xffffffffu, mx, 2));
            mx = fmaxf(mx, __shfl_xor_sync(0xffffffffu, mx, 4));
            mx = fmaxf(mx, __shfl_xor_sync(0xffffffffu, mx, 8));
            const float m_new = fmaxf(m[i], mx);
            const float alpha = __expf(m[i] - m_new);
            float rs = 0.f;
            #pragma unroll
            for (int j = 0; j < 4; ++j) {
                const float p = __expf(s[i][j] - m_new);
                s[i][j] = p;
                rs += p;
            }
            rs += __shfl_xor_sync(0xffffffffu, rs, 1);
            rs += __shfl_xor_sync(0xffffffffu, rs, 2);
            rs += __shfl_xor_sync(0xffffffffu, rs, 4);
            rs += __shfl_xor_sync(0xffffffffu, rs, 8);
            l[i] = l[i] * alpha + rs;
            m[i] = m_new;
            #pragma unroll
            for (int j = 0; j < 4; ++j) O[i][j] *= alpha;
        }

        // Stash P to shared for the PV product
        #pragma unroll
        for (int i = 0; i < 4; ++i)
            #pragma unroll
            for (int j = 0; j < 4; ++j)
                sP[(r0 + i) * PITCH + c0 + j] = s[i][j];
        __syncwarp();

        // O += P @ V
        #pragma unroll 8
        for (int c = 0; c < 64; ++c) {
            float pv[4], vv[4];
            #pragma unroll
            for (int i = 0; i < 4; ++i) pv[i] = sP[(r0 + i) * PITCH + c];
            #pragma unroll
            for (int j = 0; j < 4; ++j) vv[j] = sV[c * PITCH + c0 + j];
            #pragma unroll
            for (int i = 0; i < 4; ++i)
                #pragma unroll
                for (int j = 0; j < 4; ++j)
                    O[i][j] = fmaf(pv[i], vv[j], O[i][j]);
        }
        __syncwarp();
    }

    // Finalize and write to [B, S, H*HD]
    #pragma unroll
    for (int i = 0; i < 4; ++i) {
        const float inv = 1.0f / l[i];
        const long row = (long)(b * SS + q0 + r0 + i) * EE + h * 64 + c0;
        #pragma unroll
        for (int j = 0; j < 4; ++j)
            g_att[row + j] = O[i][j] * inv;
    }
}

// ---------------------------------------------------------------------------
// Kernel 3: output projection C[4096,1024] = A @ W^T + b
// 64x64 tile per block, 256 threads, 4x4 micro-tile, K-chunk 16.
// ---------------------------------------------------------------------------
__global__ void __launch_bounds__(256) proj_kernel(
    const float* __restrict__ W, const float* __restrict__ bias,
    float* __restrict__ out)
{
    __shared__ float sA[16][64];
    __shared__ float sB[16][64];

    const int tid = threadIdx.x;
    const int jb = blockIdx.x;   // col tile 0..15
    const int ib = blockIdx.y;   // row tile 0..63
    const int ty = tid >> 4, tx = tid & 15;

    float acc[4][4];
    #pragma unroll
    for (int i = 0; i < 4; ++i)
        #pragma unroll
        for (int j = 0; j < 4; ++j) acc[i][j] = 0.f;

    const int lr = tid >> 2;       // 0..63 (row within tile)
    const int lq = tid & 3;        // 0..3  (which float4 in k-chunk)

    for (int k0 = 0; k0 < 1024; k0 += 16) {
        __syncthreads();
        float4 a = *(const float4*)(g_att + (long)(ib * 64 + lr) * 1024 + k0 + lq * 4);
        float4 w = *(const float4*)(W     + (long)(jb * 64 + lr) * 1024 + k0 + lq * 4);
        sA[lq * 4 + 0][lr] = a.x; sA[lq * 4 + 1][lr] = a.y;
        sA[lq * 4 + 2][lr] = a.z; sA[lq * 4 + 3][lr] = a.w;
        sB[lq * 4 + 0][lr] = w.x; sB[lq * 4 + 1][lr] = w.y;
        sB[lq * 4 + 2][lr] = w.z; sB[lq * 4 + 3][lr] = w.w;
        __syncthreads();

        #pragma unroll
        for (int kk = 0; kk < 16; ++kk) {
            const float4 av = *(const float4*)&sA[kk][ty * 4];
            const float4 bv = *(const float4*)&sB[kk][tx * 4];
            const float aa[4] = {av.x, av.y, av.z, av.w};
            const float bb[4] = {bv.x, bv.y, bv.z, bv.w};
            #pragma unroll
            for (int i = 0; i < 4; ++i)
                #pragma unroll
                for (int j = 0; j < 4; ++j)
                    acc[i][j] = fmaf(aa[i], bb[j], acc[i][j]);
        }
    }

    #pragma unroll
    for (int i = 0; i < 4; ++i) {
        const long row = (long)(ib * 64 + ty * 4 + i) * 1024 + jb * 64 + tx * 4;
        #pragma unroll
        for (int j = 0; j < 4; ++j)
            out[row + j] = acc[i][j] + bias[jb * 64 + tx * 4 + j];
    }
}

// ---------------------------------------------------------------------------
extern "C" void kernel_launch(void* const* d_in, const int* in_sizes, int n_in,
                              void* d_out, int out_size)
{
    const float* x   = (const float*)d_in[0];
    const float* Wq  = (const float*)d_in[1];
    const float* bq  = (const float*)d_in[2];
    const float* Wk  = (const float*)d_in[3];
    const float* bk  = (const float*)d_in[4];
    const float* Wv  = (const float*)d_in[5];
    const float* bv  = (const float*)d_in[6];
    const float* pw  = (const float*)d_in[7];
    const float* pb  = (const float*)d_in[8];
    float* out = (float*)d_out;

    const int qkv_smem  = (3 * 4096 + TOK * EE) * (int)sizeof(float);     // 64 KB
    const int attn_smem = 4 * 64 * PITCH * (int)sizeof(float);            // ~65 KB
    cudaFuncSetAttribute(qkv_kernel,  cudaFuncAttributeMaxDynamicSharedMemorySize, qkv_smem);
    cudaFuncSetAttribute(attn_kernel, cudaFuncAttributeMaxDynamicSharedMemorySize, attn_smem);

    qkv_kernel<<<(BB * SS) / TOK, 256, qkv_smem>>>(x, Wq, bq, Wk, bk, Wv, bv);
    attn_kernel<<<dim3(SS / 64, HH, BB), 256, attn_smem>>>();
    proj_kernel<<<dim3(EE / 64, (BB * SS) / 64), 256>>>(pw, pb, out);
}

// round 3
// speedup vs baseline: 1.2876x; 1.2876x over previous
#include <cuda_runtime.h>
#include <math.h>

// Problem constants
#define BB 2
#define SS 2048
#define EE 1024
#define HH 16
#define HD 64
#define SCALE 0.125f   // 1/sqrt(64)

typedef unsigned long long ull;

// Packed f32x2 helpers (Blackwell FFMA2 path — only reachable via PTX)
#define FMA2(d, a, b, c) asm("fma.rn.f32x2 %0, %1, %2, %3;" : "=l"(d) : "l"(a), "l"(b), "l"(c))
#define MUL2(d, a, b)    asm("mul.rn.f32x2 %0, %1, %2;"     : "=l"(d) : "l"(a), "l"(b))
#define PACK2(d, lo, hi) asm("mov.b64 %0, {%1, %2};"        : "=l"(d) : "f"(lo), "f"(hi))
#define UNPACK2(lo, hi, s) asm("mov.b64 {%0, %1}, %2;"      : "=f"(lo), "=f"(hi) : "l"(s))

// Scratch: q,k,v in [B,H,S,HD]; att in [B,S,E]
__device__ float g_q[BB*HH*SS*HD];
__device__ float g_k[BB*HH*SS*HD];
__device__ float g_v[BB*HH*SS*HD];
__device__ float g_att[BB*SS*EE];

// ---------------------------------------------------------------------------
// Kernel 1: fused QKV projection. Weights transposed in SMEM (pitch 66,
// conflict-free), f32x2 over output-dim pairs.
// grid = B*S/TOK blocks, 256 threads.
// ---------------------------------------------------------------------------
#define TOK 4
#define WP 66            // weight pitch (k-major): sW[k*66 + d]
__global__ void __launch_bounds__(256) qkv_kernel(
    const float* __restrict__ x,
    const float* __restrict__ Wq, const float* __restrict__ bq,
    const float* __restrict__ Wk, const float* __restrict__ bk,
    const float* __restrict__ Wv, const float* __restrict__ bv)
{
    extern __shared__ float sm[];
    float* sWq = sm;                 // 64*66
    float* sWk = sWq + 64 * WP;
    float* sWv = sWk + 64 * WP;
    float* sX  = sWv + 64 * WP;      // TOK * 1024

    const int tid = threadIdx.x;

    // Transposed weight load: sW[k*66 + d] = W[d*64 + k]
    for (int i = tid; i < 4096; i += 256) {
        const int d = i >> 6, k = i & 63;
        sWq[k * WP + d] = Wq[i];
        sWk[k * WP + d] = Wk[i];
        sWv[k * WP + d] = Wv[i];
    }
    const long base_tok = (long)blockIdx.x * TOK;
    const float* xrow = x + base_tok * EE;
    for (int i = tid; i < TOK * EE; i += 256) sX[i] = xrow[i];
    __syncthreads();

    const int dp = (tid & 31) * 2;   // output-dim pair base (0..62)
    const int hg = tid >> 5;         // head group 0..7

    ull bq2, bk2, bv2;
    PACK2(bq2, bq[dp], bq[dp + 1]);
    PACK2(bk2, bk[dp], bk[dp + 1]);
    PACK2(bv2, bv[dp], bv[dp + 1]);

    #pragma unroll
    for (int oh = 0; oh < 2; ++oh) {
        const int h = hg + oh * 8;       // head 0..15
        ull aq[TOK], ak[TOK], av[TOK];
        #pragma unroll
        for (int t = 0; t < TOK; ++t) { aq[t] = bq2; ak[t] = bk2; av[t] = bv2; }

        #pragma unroll 8
        for (int k2 = 0; k2 < 64; ++k2) {
            const ull wq2 = *(const ull*)(sWq + k2 * WP + dp);
            const ull wk2 = *(const ull*)(sWk + k2 * WP + dp);
            const ull wv2 = *(const ull*)(sWv + k2 * WP + dp);
            #pragma unroll
            for (int t = 0; t < TOK; ++t) {
                const float xv = sX[t * EE + h * 64 + k2];
                ull xd; PACK2(xd, xv, xv);
                FMA2(aq[t], wq2, xd, aq[t]);
                FMA2(ak[t], wk2, xd, ak[t]);
                FMA2(av[t], wv2, xd, av[t]);
            }
        }
        #pragma unroll
        for (int t = 0; t < TOK; ++t) {
            const long tok = base_tok + t;
            const int b = (int)(tok >> 11);
            const int s = (int)(tok & 2047);
            const long o = (((long)(b * HH + h) * SS + s) * HD) + dp;
            *(ull*)(g_q + o) = aq[t];
            *(ull*)(g_k + o) = ak[t];
            *(ull*)(g_v + o) = av[t];
        }
    }
}

// ---------------------------------------------------------------------------
// Kernel 2: causal flash attention, fp32 with f32x2 math.
// 128-row Q blocks, 64-key K blocks. 256 threads, 8x4 micro-tile
// (accumulated as 4 row-pairs x 4 cols in f32x2).
// SMEM: Q^T [d][row] pitch 132, P^T [key][row] pitch 132,
//       K^T [d][key] pitch 68, V [key][d] pitch 68.
// ---------------------------------------------------------------------------
#define PQ 132
#define PK 68
__global__ void __launch_bounds__(256, 2) attn_kernel()
{
    extern __shared__ float sm[];
    float* sQT = sm;                 // 64 * 132
    float* sPT = sQT + 64 * PQ;      // 64 * 132
    float* sKT = sPT + 64 * PQ;      // 64 * 68
    float* sV  = sKT + 64 * PK;      // 64 * 68

    const int tid = threadIdx.x;
    const int qb = (int)(gridDim.x - 1 - blockIdx.x);   // big blocks first
    const int h  = blockIdx.y;
    const int b  = blockIdx.z;

    const long head_off = (long)(b * HH + h) * SS * HD;
    const float* Qg = g_q + head_off;
    const float* Kg = g_k + head_off;
    const float* Vg = g_v + head_off;

    const int q0 = qb * 128;
    const int ty = tid >> 4, tx = tid & 15;
    const int r0 = ty * 8;           // 8 rows per thread
    const int c0 = tx * 4;           // 4 cols per thread

    // Load Q transposed + pre-scaled: sQT[d][row]
    for (int i = tid; i < 128 * 16; i += 256) {
        const int r  = i >> 4;
        const int c4 = (i & 15) * 4;
        float4 v = *(const float4*)(Qg + (long)(q0 + r) * HD + c4);
        sQT[(c4 + 0) * PQ + r] = v.x * SCALE;
        sQT[(c4 + 1) * PQ + r] = v.y * SCALE;
        sQT[(c4 + 2) * PQ + r] = v.z * SCALE;
        sQT[(c4 + 3) * PQ + r] = v.w * SCALE;
    }

    ull O2[4][4];
    float mrow[8], lrow[8];
    #pragma unroll
    for (int p = 0; p < 4; ++p)
        #pragma unroll
        for (int j = 0; j < 4; ++j) O2[p][j] = 0ull;
    #pragma unroll
    for (int i = 0; i < 8; ++i) { mrow[i] = -INFINITY; lrow[i] = 0.f; }

    const int kbmax = 2 * qb + 1;
    for (int kb = 0; kb <= kbmax; ++kb) {
        const int k0 = kb * 64;
        __syncthreads();
        // Load K transposed, V row-major
        for (int i = tid; i < 64 * 16; i += 256) {
            const int r  = i >> 4;
            const int c4 = (i & 15) * 4;
            float4 kf = *(const float4*)(Kg + (long)(k0 + r) * HD + c4);
            sKT[(c4 + 0) * PK + r] = kf.x;
            sKT[(c4 + 1) * PK + r] = kf.y;
            sKT[(c4 + 2) * PK + r] = kf.z;
            sKT[(c4 + 3) * PK + r] = kf.w;
            float4 vf = *(const float4*)(Vg + (long)(k0 + r) * HD + c4);
            *(float4*)(sV + r * PK + c4) = vf;
        }
        __syncthreads();

        // Scores: s = (Q*scale) @ K^T  (f32x2, row pairs)
        ull s2[4][4];
        #pragma unroll
        for (int p = 0; p < 4; ++p)
            #pragma unroll
            for (int j = 0; j < 4; ++j) s2[p][j] = 0ull;

        #pragma unroll 8
        for (int d = 0; d < 64; ++d) {
            const float* qp_ = sQT + d * PQ + r0;
            const ulonglong2 qa = *(const ulonglong2*)qp_;
            const ulonglong2 qc = *(const ulonglong2*)(qp_ + 4);
            const ull qpr[4] = {qa.x, qa.y, qc.x, qc.y};
            const float4 kf = *(const float4*)(sKT + d * PK + c0);
            ull kd[4];
            PACK2(kd[0], kf.x, kf.x); PACK2(kd[1], kf.y, kf.y);
            PACK2(kd[2], kf.z, kf.z); PACK2(kd[3], kf.w, kf.w);
            #pragma unroll
            for (int p = 0; p < 4; ++p)
                #pragma unroll
                for (int j = 0; j < 4; ++j)
                    FMA2(s2[p][j], qpr[p], kd[j], s2[p][j]);
        }

        // Unpack scores
        float sf[8][4];
        #pragma unroll
        for (int p = 0; p < 4; ++p)
            #pragma unroll
            for (int j = 0; j < 4; ++j)
                UNPACK2(sf[2 * p][j], sf[2 * p + 1][j], s2[p][j]);

        // Causal mask (only blocks overlapping the diagonal)
        if (kb >= 2 * qb) {
            #pragma unroll
            for (int ri = 0; ri < 8; ++ri)
                #pragma unroll
                for (int j = 0; j < 4; ++j)
                    if (k0 + c0 + j > q0 + r0 + ri) sf[ri][j] = -1e20f;
        }

        // Online softmax
        float alpha[8];
        #pragma unroll
        for (int ri = 0; ri < 8; ++ri) {
            float mx = fmaxf(fmaxf(sf[ri][0], sf[ri][1]), fmaxf(sf[ri][2], sf[ri][3]));
            mx = fmaxf(mx, __shfl_xor_sync(0xffffffffu, mx, 1));
            mx = fmaxf(mx, __shfl_xor_sync(0xffffffffu, mx, 2));
            mx = fmaxf(mx, __shfl_xor_sync(0xffffffffu, mx, 4));
            mx = fmaxf(mx, __shfl_xor_sync(0xffffffffu, mx, 8));
            const float mn = fmaxf(mrow[ri], mx);
            alpha[ri] = __expf(mrow[ri] - mn);
            float rs = 0.f;
            #pragma unroll
            for (int j = 0; j < 4; ++j) {
                const float p = __expf(sf[ri][j] - mn);
                sf[ri][j] = p;
                rs += p;
            }
            rs += __shfl_xor_sync(0xffffffffu, rs, 1);
            rs += __shfl_xor_sync(0xffffffffu, rs, 2);
            rs += __shfl_xor_sync(0xffffffffu, rs, 4);
            rs += __shfl_xor_sync(0xffffffffu, rs, 8);
            lrow[ri] = lrow[ri] * alpha[ri] + rs;
            mrow[ri] = mn;
            // Store P transposed: sPT[key][row]
            #pragma unroll
            for (int j = 0; j < 4; ++j)
                sPT[(c0 + j) * PQ + r0 + ri] = sf[ri][j];
        }
        // Rescale O by alpha (packed per row-pair)
        #pragma unroll
        for (int p = 0; p < 4; ++p) {
            ull ap; PACK2(ap, alpha[2 * p], alpha[2 * p + 1]);
            #pragma unroll
            for (int j = 0; j < 4; ++j)
                MUL2(O2[p][j], O2[p][j], ap);
        }
        __syncthreads();

        // O += P @ V  (f32x2, row pairs)
        #pragma unroll 8
        for (int c = 0; c < 64; ++c) {
            const float* pp_ = sPT + c * PQ + r0;
            const ulonglong2 pa = *(const ulonglong2*)pp_;
            const ulonglong2 pc = *(const ulonglong2*)(pp_ + 4);
            const ull ppr[4] = {pa.x, pa.y, pc.x, pc.y};
            const float4 vf = *(const float4*)(sV + c * PK + c0);
            ull vd[4];
            PACK2(vd[0], vf.x, vf.x); PACK2(vd[1], vf.y, vf.y);
            PACK2(vd[2], vf.z, vf.z); PACK2(vd[3], vf.w, vf.w);
            #pragma unroll
            for (int p = 0; p < 4; ++p)
                #pragma unroll
                for (int j = 0; j < 4; ++j)
                    FMA2(O2[p][j], ppr[p], vd[j], O2[p][j]);
        }
    }

    // Finalize and write [B, S, H*HD]
    #pragma unroll
    for (int p = 0; p < 4; ++p) {
        float lo[4], hi[4];
        #pragma unroll
        for (int j = 0; j < 4; ++j) UNPACK2(lo[j], hi[j], O2[p][j]);
        {
            const int ri = 2 * p;
            const float inv = 1.0f / lrow[ri];
            float4 o = {lo[0] * inv, lo[1] * inv, lo[2] * inv, lo[3] * inv};
            *(float4*)(g_att + (long)(b * SS + q0 + r0 + ri) * EE + h * 64 + c0) = o;
        }
        {
            const int ri = 2 * p + 1;
            const float inv = 1.0f / lrow[ri];
            float4 o = {hi[0] * inv, hi[1] * inv, hi[2] * inv, hi[3] * inv};
            *(float4*)(g_att + (long)(b * SS + q0 + r0 + ri) * EE + h * 64 + c0) = o;
        }
    }
}

// ---------------------------------------------------------------------------
// Kernel 3: output projection C[4096,1024] = A @ W^T + b
// 128x128 tile per block, 256 threads, 8x8 micro-tile in f32x2 row pairs.
// SMEM k-major, pitch 132.
// ---------------------------------------------------------------------------
#define GP 132
__global__ void __launch_bounds__(256, 2) proj_kernel(
    const float* __restrict__ W, const float* __restrict__ bias,
    float* __restrict__ out)
{
    __shared__ float sA[16 * GP];
    __shared__ float sB[16 * GP];

    const int tid = threadIdx.x;
    const int jb = blockIdx.x;    // col tile 0..7
    const int ib = blockIdx.y;    // row tile 0..31
    const int ty = tid >> 4, tx = tid & 15;
    const int r0 = ty * 8;        // 8 rows (4 pairs)
    const int c0 = tx * 8;        // 8 cols

    ull acc[4][8];
    #pragma unroll
    for (int p = 0; p < 4; ++p)
        #pragma unroll
        for (int j = 0; j < 8; ++j) acc[p][j] = 0ull;

    const int lr = tid >> 1;      // row within tile 0..127
    const int lh = tid & 1;       // which 8-col half of the k-chunk

    for (int k0 = 0; k0 < 1024; k0 += 16) {
        __syncthreads();
        const float* Ab = g_att + (long)(ib * 128 + lr) * 1024 + k0 + lh * 8;
        const float* Wb = W     + (long)(jb * 128 + lr) * 1024 + k0 + lh * 8;
        float4 a0 = *(const float4*)(Ab);
        float4 a1 = *(const float4*)(Ab + 4);
        float4 w0 = *(const float4*)(Wb);
        float4 w1 = *(const float4*)(Wb + 4);
        const int kbase = lh * 8;
        sA[(kbase + 0) * GP + lr] = a0.x; sA[(kbase + 1) * GP + lr] = a0.y;
        sA[(kbase + 2) * GP + lr] = a0.z; sA[(kbase + 3) * GP + lr] = a0.w;
        sA[(kbase + 4) * GP + lr] = a1.x; sA[(kbase + 5) * GP + lr] = a1.y;
        sA[(kbase + 6) * GP + lr] = a1.z; sA[(kbase + 7) * GP + lr] = a1.w;
        sB[(kbase + 0) * GP + lr] = w0.x; sB[(kbase + 1) * GP + lr] = w0.y;
        sB[(kbase + 2) * GP + lr] = w0.z; sB[(kbase + 3) * GP + lr] = w0.w;
        sB[(kbase + 4) * GP + lr] = w1.x; sB[(kbase + 5) * GP + lr] = w1.y;
        sB[(kbase + 6) * GP + lr] = w1.z; sB[(kbase + 7) * GP + lr] = w1.w;
        __syncthreads();

        #pragma unroll
        for (int kk = 0; kk < 16; ++kk) {
            const float* ap_ = sA + kk * GP + r0;
            const ulonglong2 aa = *(const ulonglong2*)ap_;
            const ulonglong2 ac = *(const ulonglong2*)(ap_ + 4);
            const ull apr[4] = {aa.x, aa.y, ac.x, ac.y};
            const float4 b0 = *(const float4*)(sB + kk * GP + c0);
            const float4 b1 = *(const float4*)(sB + kk * GP + c0 + 4);
            ull bd[8];
            PACK2(bd[0], b0.x, b0.x); PACK2(bd[1], b0.y, b0.y);
            PACK2(bd[2], b0.z, b0.z); PACK2(bd[3], b0.w, b0.w);
            PACK2(bd[4], b1.x, b1.x); PACK2(bd[5], b1.y, b1.y);
            PACK2(bd[6], b1.z, b1.z); PACK2(bd[7], b1.w, b1.w);
            #pragma unroll
            for (int p = 0; p < 4; ++p)
                #pragma unroll
                for (int j = 0; j < 8; ++j)
                    FMA2(acc[p][j], apr[p], bd[j], acc[p][j]);
        }
    }

    const float4 bs0 = *(const float4*)(bias + jb * 128 + c0);
    const float4 bs1 = *(const float4*)(bias + jb * 128 + c0 + 4);
    const float bb[8] = {bs0.x, bs0.y, bs0.z, bs0.w, bs1.x, bs1.y, bs1.z, bs1.w};

    #pragma unroll
    for (int p = 0; p < 4; ++p) {
        float lo[8], hi[8];
        #pragma unroll
        for (int j = 0; j < 8; ++j) UNPACK2(lo[j], hi[j], acc[p][j]);
        float* orow0 = out + (long)(ib * 128 + r0 + 2 * p) * 1024 + jb * 128 + c0;
        float* orow1 = orow0 + 1024;
        float4 o00 = {lo[0] + bb[0], lo[1] + bb[1], lo[2] + bb[2], lo[3] + bb[3]};
        float4 o01 = {lo[4] + bb[4], lo[5] + bb[5], lo[6] + bb[6], lo[7] + bb[7]};
        float4 o10 = {hi[0] + bb[0], hi[1] + bb[1], hi[2] + bb[2], hi[3] + bb[3]};
        float4 o11 = {hi[4] + bb[4], hi[5] + bb[5], hi[6] + bb[6], hi[7] + bb[7]};
        *(float4*)(orow0)     = o00;
        *(float4*)(orow0 + 4) = o01;
        *(float4*)(orow1)     = o10;
        *(float4*)(orow1 + 4) = o11;
    }
}

// ---------------------------------------------------------------------------
extern "C" void kernel_launch(void* const* d_in, const int* in_sizes, int n_in,
                              void* d_out, int out_size)
{
    const float* x   = (const float*)d_in[0];
    const float* Wq  = (const float*)d_in[1];
    const float* bq  = (const float*)d_in[2];
    const float* Wk  = (const float*)d_in[3];
    const float* bk  = (const float*)d_in[4];
    const float* Wv  = (const float*)d_in[5];
    const float* bv  = (const float*)d_in[6];
    const float* pw  = (const float*)d_in[7];
    const float* pb  = (const float*)d_in[8];
    float* out = (float*)d_out;

    const int qkv_smem  = (3 * 64 * WP + TOK * EE) * (int)sizeof(float);          // ~65.5 KB
    const int attn_smem = (2 * 64 * PQ + 2 * 64 * PK) * (int)sizeof(float);       // 100 KB
    cudaFuncSetAttribute(qkv_kernel,  cudaFuncAttributeMaxDynamicSharedMemorySize, qkv_smem);
    cudaFuncSetAttribute(attn_kernel, cudaFuncAttributeMaxDynamicSharedMemorySize, attn_smem);

    qkv_kernel<<<(BB * SS) / TOK, 256, qkv_smem>>>(x, Wq, bq, Wk, bk, Wv, bv);
    attn_kernel<<<dim3(SS / 128, HH, BB), 256, attn_smem>>>();
    proj_kernel<<<dim3(EE / 128, (BB * SS) / 128), 256>>>(pw, pb, out);
}

// round 8
// speedup vs baseline: 2.0117x; 1.5623x over previous
#include <cuda_runtime.h>
#include <math.h>

// Problem constants
#define BB 2
#define SS 2048
#define EE 1024
#define HH 16
#define HD 64
#define SCALE 0.125f   // 1/sqrt(64)

typedef unsigned long long ull;
typedef unsigned int uint;

// Packed f32x2 helpers (Blackwell FFMA2 path — only reachable via PTX)
#define FMA2(d, a, b, c) asm("fma.rn.f32x2 %0, %1, %2, %3;" : "=l"(d) : "l"(a), "l"(b), "l"(c))
#define MUL2(d, a, b)    asm("mul.rn.f32x2 %0, %1, %2;"     : "=l"(d) : "l"(a), "l"(b))
#define PACK2(d, lo, hi) asm("mov.b64 %0, {%1, %2};"        : "=l"(d) : "f"(lo), "f"(hi))
#define UNPACK2(lo, hi, s) asm("mov.b64 {%0, %1}, %2;"      : "=f"(lo), "=f"(hi) : "l"(s))

#define CVT_TF32(u, f) asm("cvt.rna.tf32.f32 %0, %1;" : "=r"(u) : "f"(f))

// mma.sync m16n8k8 tf32: C(16x8,f32) += A(16x8,tf32) * B(8x8,tf32)
// A row-major frag: a0=(g,q) a1=(g+8,q) a2=(g,q+4) a3=(g+8,q+4); g=lane>>2, q=lane&3
// B col-major frag: b0=(k=q, n=g) b1=(k=q+4, n=g)
// C frag: c0=(g,2q) c1=(g,2q+1) c2=(g+8,2q) c3=(g+8,2q+1)
__device__ __forceinline__ void mma_tf32(float* c, const uint* a, uint b0, uint b1) {
    asm volatile("mma.sync.aligned.m16n8k8.row.col.f32.tf32.tf32.f32 "
        "{%0,%1,%2,%3}, {%4,%5,%6,%7}, {%8,%9}, {%0,%1,%2,%3};"
        : "+f"(c[0]), "+f"(c[1]), "+f"(c[2]), "+f"(c[3])
        : "r"(a[0]), "r"(a[1]), "r"(a[2]), "r"(a[3]), "r"(b0), "r"(b1));
}

// Scratch: q,k,v in [B,H,S,HD]; att in [B,S,E]
__device__ float g_q[BB*HH*SS*HD];
__device__ float g_k[BB*HH*SS*HD];
__device__ float g_v[BB*HH*SS*HD];
__device__ float g_att[BB*SS*EE];

// ---------------------------------------------------------------------------
// Kernel 1: fused QKV projection (unchanged from R1 win)
// ---------------------------------------------------------------------------
#define TOK 4
#define WP 66
__global__ void __launch_bounds__(256) qkv_kernel(
    const float* __restrict__ x,
    const float* __restrict__ Wq, const float* __restrict__ bq,
    const float* __restrict__ Wk, const float* __restrict__ bk,
    const float* __restrict__ Wv, const float* __restrict__ bv)
{
    extern __shared__ float sm[];
    float* sWq = sm;
    float* sWk = sWq + 64 * WP;
    float* sWv = sWk + 64 * WP;
    float* sX  = sWv + 64 * WP;

    const int tid = threadIdx.x;

    for (int i = tid; i < 4096; i += 256) {
        const int d = i >> 6, k = i & 63;
        sWq[k * WP + d] = Wq[i];
        sWk[k * WP + d] = Wk[i];
        sWv[k * WP + d] = Wv[i];
    }
    const long base_tok = (long)blockIdx.x * TOK;
    const float* xrow = x + base_tok * EE;
    for (int i = tid; i < TOK * EE; i += 256) sX[i] = xrow[i];
    __syncthreads();

    const int dp = (tid & 31) * 2;
    const int hg = tid >> 5;

    ull bq2, bk2, bv2;
    PACK2(bq2, bq[dp], bq[dp + 1]);
    PACK2(bk2, bk[dp], bk[dp + 1]);
    PACK2(bv2, bv[dp], bv[dp + 1]);

    #pragma unroll
    for (int oh = 0; oh < 2; ++oh) {
        const int h = hg + oh * 8;
        ull aq[TOK], ak[TOK], av[TOK];
        #pragma unroll
        for (int t = 0; t < TOK; ++t) { aq[t] = bq2; ak[t] = bk2; av[t] = bv2; }

        #pragma unroll 8
        for (int k2 = 0; k2 < 64; ++k2) {
            const ull wq2 = *(const ull*)(sWq + k2 * WP + dp);
            const ull wk2 = *(const ull*)(sWk + k2 * WP + dp);
            const ull wv2 = *(const ull*)(sWv + k2 * WP + dp);
            #pragma unroll
            for (int t = 0; t < TOK; ++t) {
                const float xv = sX[t * EE + h * 64 + k2];
                ull xd; PACK2(xd, xv, xv);
                FMA2(aq[t], wq2, xd, aq[t]);
                FMA2(ak[t], wk2, xd, ak[t]);
                FMA2(av[t], wv2, xd, av[t]);
            }
        }
        #pragma unroll
        for (int t = 0; t < TOK; ++t) {
            const long tok = base_tok + t;
            const int b = (int)(tok >> 11);
            const int s = (int)(tok & 2047);
            const long o = (((long)(b * HH + h) * SS + s) * HD) + dp;
            *(ull*)(g_q + o) = aq[t];
            *(ull*)(g_k + o) = ak[t];
            *(ull*)(g_v + o) = av[t];
        }
    }
}

// ---------------------------------------------------------------------------
// Kernel 2: causal flash attention via mma.sync tf32 (m16n8k8).
// BR=128 (8 warps x 16 rows), BC=64. Q in registers, K/V/P in SMEM pitch 72
// (conflict-free for all fragment access patterns). P is warp-private in SMEM.
// ---------------------------------------------------------------------------
#define PT 72
__global__ void __launch_bounds__(256) attn_kernel()
{
    extern __shared__ float sm[];
    float* sK  = sm;                  // [64 keys][64 d]  pitch 72
    float* sV  = sK + 64 * PT;        // [64 keys][64 d]  pitch 72
    float* sPQ = sV + 64 * PT;        // [128 rows][64]   pitch 72 (Q staging, then P)
    uint* sKu  = (uint*)sK;
    uint* sVu  = (uint*)sV;
    uint* sPQu = (uint*)sPQ;

    const int tid  = threadIdx.x;
    const int warp = tid >> 5;
    const int lane = tid & 31;
    const int g = lane >> 2;          // 0..7
    const int qd = lane & 3;          // 0..3

    const int qb = (int)(gridDim.x - 1 - blockIdx.x);   // big blocks first
    const int h  = blockIdx.y;
    const int b  = blockIdx.z;

    const long head_off = (long)(b * HH + h) * SS * HD;
    const float* Qg = g_q + head_off;
    const float* Kg = g_k + head_off;
    const float* Vg = g_v + head_off;

    const int q0  = qb * 128;
    const int r0w = warp * 16;        // warp's row base inside the Q tile

    // --- Stage Q (scaled, tf32) into sPQ, then lift into A-fragments ---
    for (int i = tid; i < 128 * 16; i += 256) {
        const int r  = i >> 4;
        const int c4 = (i & 15) * 4;
        float4 v = *(const float4*)(Qg + (long)(q0 + r) * HD + c4);
        uint u0, u1, u2, u3;
        CVT_TF32(u0, v.x * SCALE); CVT_TF32(u1, v.y * SCALE);
        CVT_TF32(u2, v.z * SCALE); CVT_TF32(u3, v.w * SCALE);
        uint* dst = sPQu + r * PT + c4;
        dst[0] = u0; dst[1] = u1; dst[2] = u2; dst[3] = u3;
    }
    __syncthreads();

    uint qf[8][4];
    #pragma unroll
    for (int t = 0; t < 8; ++t) {
        qf[t][0] = sPQu[(r0w + g)     * PT + 8 * t + qd];
        qf[t][1] = sPQu[(r0w + g + 8) * PT + 8 * t + qd];
        qf[t][2] = sPQu[(r0w + g)     * PT + 8 * t + qd + 4];
        qf[t][3] = sPQu[(r0w + g + 8) * PT + 8 * t + qd + 4];
    }
    // After this point each warp touches only its own 16 rows of sPQ (as P).

    float o[8][4];
    #pragma unroll
    for (int j = 0; j < 8; ++j)
        #pragma unroll
        for (int r = 0; r < 4; ++r) o[j][r] = 0.f;
    float m0 = -INFINITY, m1 = -INFINITY, l0 = 0.f, l1 = 0.f;

    const int kbmax = 2 * qb + 1;
    for (int kb = 0; kb <= kbmax; ++kb) {
        const int k0 = kb * 64;
        __syncthreads();
        // Load K and V tiles row-major [key][d], tf32-converted
        for (int i = tid; i < 64 * 16; i += 256) {
            const int r  = i >> 4;
            const int c4 = (i & 15) * 4;
            float4 kf = *(const float4*)(Kg + (long)(k0 + r) * HD + c4);
            float4 vf = *(const float4*)(Vg + (long)(k0 + r) * HD + c4);
            uint k0u, k1u, k2u, k3u, v0u, v1u, v2u, v3u;
            CVT_TF32(k0u, kf.x); CVT_TF32(k1u, kf.y); CVT_TF32(k2u, kf.z); CVT_TF32(k3u, kf.w);
            CVT_TF32(v0u, vf.x); CVT_TF32(v1u, vf.y); CVT_TF32(v2u, vf.z); CVT_TF32(v3u, vf.w);
            uint* dk = sKu + r * PT + c4;
            uint* dv = sVu + r * PT + c4;
            dk[0] = k0u; dk[1] = k1u; dk[2] = k2u; dk[3] = k3u;
            dv[0] = v0u; dv[1] = v1u; dv[2] = v2u; dv[3] = v3u;
        }
        __syncthreads();

        // --- S = Q @ K^T ---  (j: key n-tiles, t: d k-steps)
        float sc[8][4];
        #pragma unroll
        for (int j = 0; j < 8; ++j)
            #pragma unroll
            for (int r = 0; r < 4; ++r) sc[j][r] = 0.f;

        #pragma unroll
        for (int t = 0; t < 8; ++t) {
            #pragma unroll
            for (int j = 0; j < 8; ++j) {
                const uint b0 = sKu[(8 * j + g) * PT + 8 * t + qd];
                const uint b1 = sKu[(8 * j + g) * PT + 8 * t + qd + 4];
                mma_tf32(sc[j], qf[t], b0, b1);
            }
        }

        // Causal mask (only the two diagonal-overlapping blocks)
        if (kb >= 2 * qb) {
            const int row0 = q0 + r0w + g;
            const int row1 = row0 + 8;
            #pragma unroll
            for (int j = 0; j < 8; ++j) {
                const int c0 = k0 + 8 * j + 2 * qd;
                if (c0     > row0) sc[j][0] = -1e20f;
                if (c0 + 1 > row0) sc[j][1] = -1e20f;
                if (c0     > row1) sc[j][2] = -1e20f;
                if (c0 + 1 > row1) sc[j][3] = -1e20f;
            }
        }

        // --- Online softmax (rows g and g+8; reduce over quad lanes) ---
        float mx0 = -INFINITY, mx1 = -INFINITY;
        #pragma unroll
        for (int j = 0; j < 8; ++j) {
            mx0 = fmaxf(mx0, fmaxf(sc[j][0], sc[j][1]));
            mx1 = fmaxf(mx1, fmaxf(sc[j][2], sc[j][3]));
        }
        mx0 = fmaxf(mx0, __shfl_xor_sync(0xffffffffu, mx0, 1));
        mx0 = fmaxf(mx0, __shfl_xor_sync(0xffffffffu, mx0, 2));
        mx1 = fmaxf(mx1, __shfl_xor_sync(0xffffffffu, mx1, 1));
        mx1 = fmaxf(mx1, __shfl_xor_sync(0xffffffffu, mx1, 2));

        const float mn0 = fmaxf(m0, mx0);
        const float mn1 = fmaxf(m1, mx1);
        const float a0 = __expf(m0 - mn0);
        const float a1 = __expf(m1 - mn1);
        float rs0 = 0.f, rs1 = 0.f;
        #pragma unroll
        for (int j = 0; j < 8; ++j) {
            sc[j][0] = __expf(sc[j][0] - mn0);
            sc[j][1] = __expf(sc[j][1] - mn0);
            sc[j][2] = __expf(sc[j][2] - mn1);
            sc[j][3] = __expf(sc[j][3] - mn1);
            rs0 += sc[j][0] + sc[j][1];
            rs1 += sc[j][2] + sc[j][3];
        }
        rs0 += __shfl_xor_sync(0xffffffffu, rs0, 1);
        rs0 += __shfl_xor_sync(0xffffffffu, rs0, 2);
        rs1 += __shfl_xor_sync(0xffffffffu, rs1, 1);
        rs1 += __shfl_xor_sync(0xffffffffu, rs1, 2);
        l0 = l0 * a0 + rs0;  m0 = mn0;
        l1 = l1 * a1 + rs1;  m1 = mn1;

        // Store P (tf32) to warp-private SMEM rows; rescale O
        #pragma unroll
        for (int j = 0; j < 8; ++j) {
            uint p0, p1, p2, p3;
            CVT_TF32(p0, sc[j][0]); CVT_TF32(p1, sc[j][1]);
            CVT_TF32(p2, sc[j][2]); CVT_TF32(p3, sc[j][3]);
            *(uint2*)(sPQu + (r0w + g)     * PT + 8 * j + 2 * qd) = make_uint2(p0, p1);
            *(uint2*)(sPQu + (r0w + g + 8) * PT + 8 * j + 2 * qd) = make_uint2(p2, p3);
            o[j][0] *= a0; o[j][1] *= a0;
            o[j][2] *= a1; o[j][3] *= a1;
        }
        __syncwarp();

        // --- O += P @ V ---  (t: key k-steps, j: d n-tiles)
        #pragma unroll
        for (int t = 0; t < 8; ++t) {
            uint af[4];
            af[0] = sPQu[(r0w + g)     * PT + 8 * t + qd];
            af[1] = sPQu[(r0w + g + 8) * PT + 8 * t + qd];
            af[2] = sPQu[(r0w + g)     * PT + 8 * t + qd + 4];
            af[3] = sPQu[(r0w + g + 8) * PT + 8 * t + qd + 4];
            #pragma unroll
            for (int j = 0; j < 8; ++j) {
                const uint b0 = sVu[(8 * t + qd)     * PT + 8 * j + g];
                const uint b1 = sVu[(8 * t + qd + 4) * PT + 8 * j + g];
                mma_tf32(o[j], af, b0, b1);
            }
        }
        __syncwarp();
    }

    // --- Finalize: O /= l, write to [B, S, H*HD] ---
    const float inv0 = 1.0f / l0;
    const float inv1 = 1.0f / l1;
    const long row0 = (long)(b * SS + q0 + r0w + g) * EE + h * 64;
    const long row1 = row0 + 8 * EE;
    #pragma unroll
    for (int j = 0; j < 8; ++j) {
        const int c = 8 * j + 2 * qd;
        *(float2*)(g_att + row0 + c) = make_float2(o[j][0] * inv0, o[j][1] * inv0);
        *(float2*)(g_att + row1 + c) = make_float2(o[j][2] * inv1, o[j][3] * inv1);
    }
}

// ---------------------------------------------------------------------------
// Kernel 3: output projection (unchanged f32x2 version)
// ---------------------------------------------------------------------------
#define GP 132
__global__ void __launch_bounds__(256, 2) proj_kernel(
    const float* __restrict__ W, const float* __restrict__ bias,
    float* __restrict__ out)
{
    __shared__ float sA[16 * GP];
    __shared__ float sB[16 * GP];

    const int tid = threadIdx.x;
    const int jb = blockIdx.x;
    const int ib = blockIdx.y;
    const int ty = tid >> 4, tx = tid & 15;
    const int r0 = ty * 8;
    const int c0 = tx * 8;

    ull acc[4][8];
    #pragma unroll
    for (int p = 0; p < 4; ++p)
        #pragma unroll
        for (int j = 0; j < 8; ++j) acc[p][j] = 0ull;

    const int lr = tid >> 1;
    const int lh = tid & 1;

    for (int k0 = 0; k0 < 1024; k0 += 16) {
        __syncthreads();
        const float* Ab = g_att + (long)(ib * 128 + lr) * 1024 + k0 + lh * 8;
        const float* Wb = W     + (long)(jb * 128 + lr) * 1024 + k0 + lh * 8;
        float4 a0 = *(const float4*)(Ab);
        float4 a1 = *(const float4*)(Ab + 4);
        float4 w0 = *(const float4*)(Wb);
        float4 w1 = *(const float4*)(Wb + 4);
        const int kbase = lh * 8;
        sA[(kbase + 0) * GP + lr] = a0.x; sA[(kbase + 1) * GP + lr] = a0.y;
        sA[(kbase + 2) * GP + lr] = a0.z; sA[(kbase + 3) * GP + lr] = a0.w;
        sA[(kbase + 4) * GP + lr] = a1.x; sA[(kbase + 5) * GP + lr] = a1.y;
        sA[(kbase + 6) * GP + lr] = a1.z; sA[(kbase + 7) * GP + lr] = a1.w;
        sB[(kbase + 0) * GP + lr] = w0.x; sB[(kbase + 1) * GP + lr] = w0.y;
        sB[(kbase + 2) * GP + lr] = w0.z; sB[(kbase + 3) * GP + lr] = w0.w;
        sB[(kbase + 4) * GP + lr] = w1.x; sB[(kbase + 5) * GP + lr] = w1.y;
        sB[(kbase + 6) * GP + lr] = w1.z; sB[(kbase + 7) * GP + lr] = w1.w;
        __syncthreads();

        #pragma unroll
        for (int kk = 0; kk < 16; ++kk) {
            const float* ap_ = sA + kk * GP + r0;
            const ulonglong2 aa = *(const ulonglong2*)ap_;
            const ulonglong2 ac = *(const ulonglong2*)(ap_ + 4);
            const ull apr[4] = {aa.x, aa.y, ac.x, ac.y};
            const float4 b0 = *(const float4*)(sB + kk * GP + c0);
            const float4 b1 = *(const float4*)(sB + kk * GP + c0 + 4);
            ull bd[8];
            PACK2(bd[0], b0.x, b0.x); PACK2(bd[1], b0.y, b0.y);
            PACK2(bd[2], b0.z, b0.z); PACK2(bd[3], b0.w, b0.w);
            PACK2(bd[4], b1.x, b1.x); PACK2(bd[5], b1.y, b1.y);
            PACK2(bd[6], b1.z, b1.z); PACK2(bd[7], b1.w, b1.w);
            #pragma unroll
            for (int p = 0; p < 4; ++p)
                #pragma unroll
                for (int j = 0; j < 8; ++j)
                    FMA2(acc[p][j], apr[p], bd[j], acc[p][j]);
        }
    }

    const float4 bs0 = *(const float4*)(bias + jb * 128 + c0);
    const float4 bs1 = *(const float4*)(bias + jb * 128 + c0 + 4);
    const float bb[8] = {bs0.x, bs0.y, bs0.z, bs0.w, bs1.x, bs1.y, bs1.z, bs1.w};

    #pragma unroll
    for (int p = 0; p < 4; ++p) {
        float lo[8], hi[8];
        #pragma unroll
        for (int j = 0; j < 8; ++j) UNPACK2(lo[j], hi[j], acc[p][j]);
        float* orow0 = out + (long)(ib * 128 + r0 + 2 * p) * 1024 + jb * 128 + c0;
        float* orow1 = orow0 + 1024;
        float4 o00 = {lo[0] + bb[0], lo[1] + bb[1], lo[2] + bb[2], lo[3] + bb[3]};
        float4 o01 = {lo[4] + bb[4], lo[5] + bb[5], lo[6] + bb[6], lo[7] + bb[7]};
        float4 o10 = {hi[0] + bb[0], hi[1] + bb[1], hi[2] + bb[2], hi[3] + bb[3]};
        float4 o11 = {hi[4] + bb[4], hi[5] + bb[5], hi[6] + bb[6], hi[7] + bb[7]};
        *(float4*)(orow0)     = o00;
        *(float4*)(orow0 + 4) = o01;
        *(float4*)(orow1)     = o10;
        *(float4*)(orow1 + 4) = o11;
    }
}

// ---------------------------------------------------------------------------
extern "C" void kernel_launch(void* const* d_in, const int* in_sizes, int n_in,
                              void* d_out, int out_size)
{
    const float* x   = (const float*)d_in[0];
    const float* Wq  = (const float*)d_in[1];
    const float* bq  = (const float*)d_in[2];
    const float* Wk  = (const float*)d_in[3];
    const float* bk  = (const float*)d_in[4];
    const float* Wv  = (const float*)d_in[5];
    const float* bv  = (const float*)d_in[6];
    const float* pw  = (const float*)d_in[7];
    const float* pb  = (const float*)d_in[8];
    float* out = (float*)d_out;

    const int qkv_smem  = (3 * 64 * WP + TOK * EE) * (int)sizeof(float);     // ~65.5 KB
    const int attn_smem = (64 * PT + 64 * PT + 128 * PT) * (int)sizeof(float); // 73.7 KB
    cudaFuncSetAttribute(qkv_kernel,  cudaFuncAttributeMaxDynamicSharedMemorySize, qkv_smem);
    cudaFuncSetAttribute(attn_kernel, cudaFuncAttributeMaxDynamicSharedMemorySize, attn_smem);

    qkv_kernel<<<(BB * SS) / TOK, 256, qkv_smem>>>(x, Wq, bq, Wk, bk, Wv, bv);
    attn_kernel<<<dim3(SS / 128, HH, BB), 256, attn_smem>>>();
    proj_kernel<<<dim3(EE / 128, (BB * SS) / 128), 256>>>(pw, pb, out);
}

// round 13
// speedup vs baseline: 3.1742x; 1.5778x over previous
#include <cuda_runtime.h>
#include <math.h>

// Problem constants
#define BB 2
#define SS 2048
#define EE 1024
#define HH 16
#define HD 64
#define SCALE 0.125f   // 1/sqrt(64)

typedef unsigned long long ull;
typedef unsigned int uint;

// Packed f32x2 helpers
#define FMA2(d, a, b, c) asm("fma.rn.f32x2 %0, %1, %2, %3;" : "=l"(d) : "l"(a), "l"(b), "l"(c))
#define MUL2(d, a, b)    asm("mul.rn.f32x2 %0, %1, %2;"     : "=l"(d) : "l"(a), "l"(b))
#define PACK2(d, lo, hi) asm("mov.b64 %0, {%1, %2};"        : "=l"(d) : "f"(lo), "f"(hi))
#define UNPACK2(lo, hi, s) asm("mov.b64 {%0, %1}, %2;"      : "=f"(lo), "=f"(hi) : "l"(s))

#define CVT_TF32(u, f) asm("cvt.rna.tf32.f32 %0, %1;" : "=r"(u) : "f"(f))

// mma.sync m16n8k8 tf32: C(16x8,f32) += A(16x8,tf32) * B(8x8,tf32)
// A row-major frag: a0=(g,q) a1=(g+8,q) a2=(g,q+4) a3=(g+8,q+4); g=lane>>2, q=lane&3
// B col-major frag: b0=(k=q, n=g) b1=(k=q+4, n=g)
// C frag: c0=(g,2q) c1=(g,2q+1) c2=(g+8,2q) c3=(g+8,2q+1)
__device__ __forceinline__ void mma_tf32(float* c, const uint* a, uint b0, uint b1) {
    asm volatile("mma.sync.aligned.m16n8k8.row.col.f32.tf32.tf32.f32 "
        "{%0,%1,%2,%3}, {%4,%5,%6,%7}, {%8,%9}, {%0,%1,%2,%3};"
        : "+f"(c[0]), "+f"(c[1]), "+f"(c[2]), "+f"(c[3])
        : "r"(a[0]), "r"(a[1]), "r"(a[2]), "r"(a[3]), "r"(b0), "r"(b1));
}

// Scratch: q,k,v in [B,H,S,HD]; att in [B,S,E]
__device__ float g_q[BB*HH*SS*HD];
__device__ float g_k[BB*HH*SS*HD];
__device__ float g_v[BB*HH*SS*HD];
__device__ float g_att[BB*SS*EE];

// ---------------------------------------------------------------------------
// Kernel 1: fused QKV projection (unchanged)
// ---------------------------------------------------------------------------
#define TOK 4
#define WP 66
__global__ void __launch_bounds__(256) qkv_kernel(
    const float* __restrict__ x,
    const float* __restrict__ Wq, const float* __restrict__ bq,
    const float* __restrict__ Wk, const float* __restrict__ bk,
    const float* __restrict__ Wv, const float* __restrict__ bv)
{
    extern __shared__ float sm[];
    float* sWq = sm;
    float* sWk = sWq + 64 * WP;
    float* sWv = sWk + 64 * WP;
    float* sX  = sWv + 64 * WP;

    const int tid = threadIdx.x;

    for (int i = tid; i < 4096; i += 256) {
        const int d = i >> 6, k = i & 63;
        sWq[k * WP + d] = Wq[i];
        sWk[k * WP + d] = Wk[i];
        sWv[k * WP + d] = Wv[i];
    }
    const long base_tok = (long)blockIdx.x * TOK;
    const float* xrow = x + base_tok * EE;
    for (int i = tid; i < TOK * EE; i += 256) sX[i] = xrow[i];
    __syncthreads();

    const int dp = (tid & 31) * 2;
    const int hg = tid >> 5;

    ull bq2, bk2, bv2;
    PACK2(bq2, bq[dp], bq[dp + 1]);
    PACK2(bk2, bk[dp], bk[dp + 1]);
    PACK2(bv2, bv[dp], bv[dp + 1]);

    #pragma unroll
    for (int oh = 0; oh < 2; ++oh) {
        const int h = hg + oh * 8;
        ull aq[TOK], ak[TOK], av[TOK];
        #pragma unroll
        for (int t = 0; t < TOK; ++t) { aq[t] = bq2; ak[t] = bk2; av[t] = bv2; }

        #pragma unroll 8
        for (int k2 = 0; k2 < 64; ++k2) {
            const ull wq2 = *(const ull*)(sWq + k2 * WP + dp);
            const ull wk2 = *(const ull*)(sWk + k2 * WP + dp);
            const ull wv2 = *(const ull*)(sWv + k2 * WP + dp);
            #pragma unroll
            for (int t = 0; t < TOK; ++t) {
                const float xv = sX[t * EE + h * 64 + k2];
                ull xd; PACK2(xd, xv, xv);
                FMA2(aq[t], wq2, xd, aq[t]);
                FMA2(ak[t], wk2, xd, ak[t]);
                FMA2(av[t], wv2, xd, av[t]);
            }
        }
        #pragma unroll
        for (int t = 0; t < TOK; ++t) {
            const long tok = base_tok + t;
            const int b = (int)(tok >> 11);
            const int s = (int)(tok & 2047);
            const long o = (((long)(b * HH + h) * SS + s) * HD) + dp;
            *(ull*)(g_q + o) = aq[t];
            *(ull*)(g_k + o) = ak[t];
            *(ull*)(g_v + o) = av[t];
        }
    }
}

// ---------------------------------------------------------------------------
// Kernel 2: causal flash attention via mma.sync tf32 (m16n8k8).
// BR=128 (8 warps x 16 rows), BC=64. Q in registers, K/V/P in SMEM pitch 72.
// NEW: register-staged prefetch of next K/V tile overlaps global latency
// with compute (LDG issued right after the tile-visibility sync).
// ---------------------------------------------------------------------------
#define PT 72
__global__ void __launch_bounds__(256) attn_kernel()
{
    extern __shared__ float sm[];
    float* sK  = sm;                  // [64 keys][64 d]  pitch 72
    float* sV  = sK + 64 * PT;
    float* sPQ = sV + 64 * PT;        // [128 rows][64]   pitch 72 (Q staging, then P)
    uint* sKu  = (uint*)sK;
    uint* sVu  = (uint*)sV;
    uint* sPQu = (uint*)sPQ;

    const int tid  = threadIdx.x;
    const int warp = tid >> 5;
    const int lane = tid & 31;
    const int g = lane >> 2;
    const int qd = lane & 3;

    const int qb = (int)(gridDim.x - 1 - blockIdx.x);   // big blocks first
    const int h  = blockIdx.y;
    const int b  = blockIdx.z;

    const long head_off = (long)(b * HH + h) * SS * HD;
    const float* Qg = g_q + head_off;
    const float* Kg = g_k + head_off;
    const float* Vg = g_v + head_off;

    const int q0  = qb * 128;
    const int r0w = warp * 16;

    // Prefetch K/V tile kb=0 into registers (overlaps with Q staging)
    float4 kreg[4], vreg[4];
    #pragma unroll
    for (int u = 0; u < 4; ++u) {
        const int i  = tid + u * 256;
        const int r  = i >> 4;
        const int c4 = (i & 15) * 4;
        kreg[u] = *(const float4*)(Kg + (long)r * HD + c4);
        vreg[u] = *(const float4*)(Vg + (long)r * HD + c4);
    }

    // Stage Q (scaled, tf32) into sPQ, then lift into A-fragments
    for (int i = tid; i < 128 * 16; i += 256) {
        const int r  = i >> 4;
        const int c4 = (i & 15) * 4;
        float4 v = *(const float4*)(Qg + (long)(q0 + r) * HD + c4);
        uint u0, u1, u2, u3;
        CVT_TF32(u0, v.x * SCALE); CVT_TF32(u1, v.y * SCALE);
        CVT_TF32(u2, v.z * SCALE); CVT_TF32(u3, v.w * SCALE);
        uint* dst = sPQu + r * PT + c4;
        dst[0] = u0; dst[1] = u1; dst[2] = u2; dst[3] = u3;
    }
    __syncthreads();

    uint qf[8][4];
    #pragma unroll
    for (int t = 0; t < 8; ++t) {
        qf[t][0] = sPQu[(r0w + g)     * PT + 8 * t + qd];
        qf[t][1] = sPQu[(r0w + g + 8) * PT + 8 * t + qd];
        qf[t][2] = sPQu[(r0w + g)     * PT + 8 * t + qd + 4];
        qf[t][3] = sPQu[(r0w + g + 8) * PT + 8 * t + qd + 4];
    }
    __syncthreads();   // everyone done reading Q from sPQ before it becomes P

    float o[8][4];
    #pragma unroll
    for (int j = 0; j < 8; ++j)
        #pragma unroll
        for (int r = 0; r < 4; ++r) o[j][r] = 0.f;
    float m0 = -INFINITY, m1 = -INFINITY, l0 = 0.f, l1 = 0.f;

    const int kbmax = 2 * qb + 1;
    for (int kb = 0; kb <= kbmax; ++kb) {
        // Store prefetched tile into SMEM (tf32)
        #pragma unroll
        for (int u = 0; u < 4; ++u) {
            const int i  = tid + u * 256;
            const int r  = i >> 4;
            const int c4 = (i & 15) * 4;
            uint a0, a1, a2, a3;
            CVT_TF32(a0, kreg[u].x); CVT_TF32(a1, kreg[u].y);
            CVT_TF32(a2, kreg[u].z); CVT_TF32(a3, kreg[u].w);
            *(uint4*)(sKu + r * PT + c4) = make_uint4(a0, a1, a2, a3);
            CVT_TF32(a0, vreg[u].x); CVT_TF32(a1, vreg[u].y);
            CVT_TF32(a2, vreg[u].z); CVT_TF32(a3, vreg[u].w);
            *(uint4*)(sVu + r * PT + c4) = make_uint4(a0, a1, a2, a3);
        }
        __syncthreads();

        // Issue next tile's loads now; they complete during compute
        if (kb < kbmax) {
            const int kn = (kb + 1) * 64;
            #pragma unroll
            for (int u = 0; u < 4; ++u) {
                const int i  = tid + u * 256;
                const int r  = i >> 4;
                const int c4 = (i & 15) * 4;
                kreg[u] = *(const float4*)(Kg + (long)(kn + r) * HD + c4);
                vreg[u] = *(const float4*)(Vg + (long)(kn + r) * HD + c4);
            }
        }

        const int k0 = kb * 64;

        // --- S = Q @ K^T ---
        float sc[8][4];
        #pragma unroll
        for (int j = 0; j < 8; ++j)
            #pragma unroll
            for (int r = 0; r < 4; ++r) sc[j][r] = 0.f;

        #pragma unroll
        for (int t = 0; t < 8; ++t) {
            #pragma unroll
            for (int j = 0; j < 8; ++j) {
                const uint b0 = sKu[(8 * j + g) * PT + 8 * t + qd];
                const uint b1 = sKu[(8 * j + g) * PT + 8 * t + qd + 4];
                mma_tf32(sc[j], qf[t], b0, b1);
            }
        }

        // Causal mask
        if (kb >= 2 * qb) {
            const int row0 = q0 + r0w + g;
            const int row1 = row0 + 8;
            #pragma unroll
            for (int j = 0; j < 8; ++j) {
                const int c0 = k0 + 8 * j + 2 * qd;
                if (c0     > row0) sc[j][0] = -1e20f;
                if (c0 + 1 > row0) sc[j][1] = -1e20f;
                if (c0     > row1) sc[j][2] = -1e20f;
                if (c0 + 1 > row1) sc[j][3] = -1e20f;
            }
        }

        // --- Online softmax ---
        float mx0 = -INFINITY, mx1 = -INFINITY;
        #pragma unroll
        for (int j = 0; j < 8; ++j) {
            mx0 = fmaxf(mx0, fmaxf(sc[j][0], sc[j][1]));
            mx1 = fmaxf(mx1, fmaxf(sc[j][2], sc[j][3]));
        }
        mx0 = fmaxf(mx0, __shfl_xor_sync(0xffffffffu, mx0, 1));
        mx0 = fmaxf(mx0, __shfl_xor_sync(0xffffffffu, mx0, 2));
        mx1 = fmaxf(mx1, __shfl_xor_sync(0xffffffffu, mx1, 1));
        mx1 = fmaxf(mx1, __shfl_xor_sync(0xffffffffu, mx1, 2));

        const float mn0 = fmaxf(m0, mx0);
        const float mn1 = fmaxf(m1, mx1);
        const float a0 = __expf(m0 - mn0);
        const float a1 = __expf(m1 - mn1);
        float rs0 = 0.f, rs1 = 0.f;
        #pragma unroll
        for (int j = 0; j < 8; ++j) {
            sc[j][0] = __expf(sc[j][0] - mn0);
            sc[j][1] = __expf(sc[j][1] - mn0);
            sc[j][2] = __expf(sc[j][2] - mn1);
            sc[j][3] = __expf(sc[j][3] - mn1);
            rs0 += sc[j][0] + sc[j][1];
            rs1 += sc[j][2] + sc[j][3];
        }
        rs0 += __shfl_xor_sync(0xffffffffu, rs0, 1);
        rs0 += __shfl_xor_sync(0xffffffffu, rs0, 2);
        rs1 += __shfl_xor_sync(0xffffffffu, rs1, 1);
        rs1 += __shfl_xor_sync(0xffffffffu, rs1, 2);
        l0 = l0 * a0 + rs0;  m0 = mn0;
        l1 = l1 * a1 + rs1;  m1 = mn1;

        // P -> warp-private SMEM rows (tf32); rescale O
        #pragma unroll
        for (int j = 0; j < 8; ++j) {
            uint p0, p1, p2, p3;
            CVT_TF32(p0, sc[j][0]); CVT_TF32(p1, sc[j][1]);
            CVT_TF32(p2, sc[j][2]); CVT_TF32(p3, sc[j][3]);
            *(uint2*)(sPQu + (r0w + g)     * PT + 8 * j + 2 * qd) = make_uint2(p0, p1);
            *(uint2*)(sPQu + (r0w + g + 8) * PT + 8 * j + 2 * qd) = make_uint2(p2, p3);
            o[j][0] *= a0; o[j][1] *= a0;
            o[j][2] *= a1; o[j][3] *= a1;
        }
        __syncwarp();

        // --- O += P @ V ---
        #pragma unroll
        for (int t = 0; t < 8; ++t) {
            uint af[4];
            af[0] = sPQu[(r0w + g)     * PT + 8 * t + qd];
            af[1] = sPQu[(r0w + g + 8) * PT + 8 * t + qd];
            af[2] = sPQu[(r0w + g)     * PT + 8 * t + qd + 4];
            af[3] = sPQu[(r0w + g + 8) * PT + 8 * t + qd + 4];
            #pragma unroll
            for (int j = 0; j < 8; ++j) {
                const uint b0 = sVu[(8 * t + qd)     * PT + 8 * j + g];
                const uint b1 = sVu[(8 * t + qd + 4) * PT + 8 * j + g];
                mma_tf32(o[j], af, b0, b1);
            }
        }
        __syncthreads();   // protect sK/sV before next iteration's store
    }

    // Finalize: O /= l, write to [B, S, H*HD]
    const float inv0 = 1.0f / l0;
    const float inv1 = 1.0f / l1;
    const long row0 = (long)(b * SS + q0 + r0w + g) * EE + h * 64;
    const long row1 = row0 + 8 * EE;
    #pragma unroll
    for (int j = 0; j < 8; ++j) {
        const int c = 8 * j + 2 * qd;
        *(float2*)(g_att + row0 + c) = make_float2(o[j][0] * inv0, o[j][1] * inv0);
        *(float2*)(g_att + row1 + c) = make_float2(o[j][2] * inv1, o[j][3] * inv1);
    }
}

// ---------------------------------------------------------------------------
// Kernel 3: output projection via tf32 mma. C[4096,1024] = A @ W^T + b.
// Block tile 128x128, 8 warps (32x64 each), K-stage 32, double-buffered SMEM
// (pitch 36, conflict-free fragment access), register-staged prefetch.
// ---------------------------------------------------------------------------
#define PP 36
#define PSTG (128 * PP)          // floats per matrix per stage buffer (4608)
__global__ void __launch_bounds__(256) proj_kernel(
    const float* __restrict__ W, const float* __restrict__ bias,
    float* __restrict__ out)
{
    extern __shared__ float smp[];
    // layout: buf0 A | buf0 W | buf1 A | buf1 W
    uint* sbuf = (uint*)smp;

    const int tid  = threadIdx.x;
    const int warp = tid >> 5;
    const int lane = tid & 31;
    const int g  = lane >> 2;
    const int qd = lane & 3;

    const int jb = blockIdx.x;            // N tile 0..7
    const int ib = blockIdx.y;            // M tile 0..31
    const int wm = (warp >> 1) * 32;      // warp M base 0..96
    const int wn = (warp & 1) * 64;       // warp N base 0/64

    float acc[2][8][4];
    #pragma unroll
    for (int mt = 0; mt < 2; ++mt)
        #pragma unroll
        for (int j = 0; j < 8; ++j)
            #pragma unroll
            for (int r = 0; r < 4; ++r) acc[mt][j][r] = 0.f;

    // Per-thread load coords (4 float4 per matrix per stage)
    // i = tid + u*256 -> row = i>>3 (0..127), c4 = (i&7)*4 (0..28)
    float4 areg[4], wreg[4];
    {
        #pragma unroll
        for (int u = 0; u < 4; ++u) {
            const int i = tid + u * 256;
            const int r = i >> 3, c4 = (i & 7) * 4;
            areg[u] = *(const float4*)(g_att + (long)(ib * 128 + r) * 1024 + c4);
            wreg[u] = *(const float4*)(W     + (long)(jb * 128 + r) * 1024 + c4);
        }
        // store stage 0 into buf0
        #pragma unroll
        for (int u = 0; u < 4; ++u) {
            const int i = tid + u * 256;
            const int r = i >> 3, c4 = (i & 7) * 4;
            uint a0, a1, a2, a3;
            CVT_TF32(a0, areg[u].x); CVT_TF32(a1, areg[u].y);
            CVT_TF32(a2, areg[u].z); CVT_TF32(a3, areg[u].w);
            *(uint4*)(sbuf + r * PP + c4) = make_uint4(a0, a1, a2, a3);
            CVT_TF32(a0, wreg[u].x); CVT_TF32(a1, wreg[u].y);
            CVT_TF32(a2, wreg[u].z); CVT_TF32(a3, wreg[u].w);
            *(uint4*)(sbuf + PSTG + r * PP + c4) = make_uint4(a0, a1, a2, a3);
        }
    }
    __syncthreads();

    const int NSTG = 1024 / 32;   // 32 stages
    for (int s = 0; s < NSTG; ++s) {
        uint* sA = sbuf + (s & 1) * 2 * PSTG;
        uint* sW = sA + PSTG;

        // Prefetch next stage into registers
        if (s + 1 < NSTG) {
            const int k0 = (s + 1) * 32;
            #pragma unroll
            for (int u = 0; u < 4; ++u) {
                const int i = tid + u * 256;
                const int r = i >> 3, c4 = (i & 7) * 4;
                areg[u] = *(const float4*)(g_att + (long)(ib * 128 + r) * 1024 + k0 + c4);
                wreg[u] = *(const float4*)(W     + (long)(jb * 128 + r) * 1024 + k0 + c4);
            }
        }

        // Compute this stage: 4 k-steps of 8
        #pragma unroll
        for (int t = 0; t < 4; ++t) {
            const int kk = t * 8;
            uint af0[4], af1[4];
            af0[0] = sA[(wm + g)      * PP + kk + qd];
            af0[1] = sA[(wm + g + 8)  * PP + kk + qd];
            af0[2] = sA[(wm + g)      * PP + kk + qd + 4];
            af0[3] = sA[(wm + g + 8)  * PP + kk + qd + 4];
            af1[0] = sA[(wm + g + 16) * PP + kk + qd];
            af1[1] = sA[(wm + g + 24) * PP + kk + qd];
            af1[2] = sA[(wm + g + 16) * PP + kk + qd + 4];
            af1[3] = sA[(wm + g + 24) * PP + kk + qd + 4];
            #pragma unroll
            for (int j = 0; j < 8; ++j) {
                const uint b0 = sW[(wn + 8 * j + g) * PP + kk + qd];
                const uint b1 = sW[(wn + 8 * j + g) * PP + kk + qd + 4];
                mma_tf32(acc[0][j], af0, b0, b1);
                mma_tf32(acc[1][j], af1, b0, b1);
            }
        }

        // Store prefetched stage into the other buffer
        if (s + 1 < NSTG) {
            uint* dA = sbuf + ((s + 1) & 1) * 2 * PSTG;
            uint* dW = dA + PSTG;
            #pragma unroll
            for (int u = 0; u < 4; ++u) {
                const int i = tid + u * 256;
                const int r = i >> 3, c4 = (i & 7) * 4;
                uint a0, a1, a2, a3;
                CVT_TF32(a0, areg[u].x); CVT_TF32(a1, areg[u].y);
                CVT_TF32(a2, areg[u].z); CVT_TF32(a3, areg[u].w);
                *(uint4*)(dA + r * PP + c4) = make_uint4(a0, a1, a2, a3);
                CVT_TF32(a0, wreg[u].x); CVT_TF32(a1, wreg[u].y);
                CVT_TF32(a2, wreg[u].z); CVT_TF32(a3, wreg[u].w);
                *(uint4*)(dW + r * PP + c4) = make_uint4(a0, a1, a2, a3);
            }
        }
        __syncthreads();
    }

    // Epilogue: add bias, write C
    #pragma unroll
    for (int mt = 0; mt < 2; ++mt) {
        const int rbase = ib * 128 + wm + mt * 16;
        #pragma unroll
        for (int j = 0; j < 8; ++j) {
            const int col = jb * 128 + wn + 8 * j + 2 * qd;
            const float b0 = bias[col], b1 = bias[col + 1];
            float* p0 = out + (long)(rbase + g) * 1024 + col;
            float* p1 = out + (long)(rbase + g + 8) * 1024 + col;
            *(float2*)p0 = make_float2(acc[mt][j][0] + b0, acc[mt][j][1] + b1);
            *(float2*)p1 = make_float2(acc[mt][j][2] + b0, acc[mt][j][3] + b1);
        }
    }
}

// ---------------------------------------------------------------------------
extern "C" void kernel_launch(void* const* d_in, const int* in_sizes, int n_in,
                              void* d_out, int out_size)
{
    const float* x   = (const float*)d_in[0];
    const float* Wq  = (const float*)d_in[1];
    const float* bq  = (const float*)d_in[2];
    const float* Wk  = (const float*)d_in[3];
    const float* bk  = (const float*)d_in[4];
    const float* Wv  = (const float*)d_in[5];
    const float* bv  = (const float*)d_in[6];
    const float* pw  = (const float*)d_in[7];
    const float* pb  = (const float*)d_in[8];
    float* out = (float*)d_out;

    const int qkv_smem  = (3 * 64 * WP + TOK * EE) * (int)sizeof(float);       // ~65.5 KB
    const int attn_smem = (64 * PT + 64 * PT + 128 * PT) * (int)sizeof(float); // 73.7 KB
    const int proj_smem = 4 * PSTG * (int)sizeof(float);                       // 73.7 KB
    cudaFuncSetAttribute(qkv_kernel,  cudaFuncAttributeMaxDynamicSharedMemorySize, qkv_smem);
    cudaFuncSetAttribute(attn_kernel, cudaFuncAttributeMaxDynamicSharedMemorySize, attn_smem);
    cudaFuncSetAttribute(proj_kernel, cudaFuncAttributeMaxDynamicSharedMemorySize, proj_smem);

    qkv_kernel<<<(BB * SS) / TOK, 256, qkv_smem>>>(x, Wq, bq, Wk, bk, Wv, bv);
    attn_kernel<<<dim3(SS / 128, HH, BB), 256, attn_smem>>>();
    proj_kernel<<<dim3(EE / 128, (BB * SS) / 128), 256, proj_smem>>>(pw, pb, out);
}

// round 14
// speedup vs baseline: 3.5452x; 1.1169x over previous
#include <cuda_runtime.h>
#include <math.h>

// Problem constants
#define BB 2
#define SS 2048
#define EE 1024
#define HH 16
#define HD 64
#define SCALE 0.125f   // 1/sqrt(64)

typedef unsigned long long ull;
typedef unsigned int uint;

// Packed f32x2 helpers
#define FMA2(d, a, b, c) asm("fma.rn.f32x2 %0, %1, %2, %3;" : "=l"(d) : "l"(a), "l"(b), "l"(c))
#define MUL2(d, a, b)    asm("mul.rn.f32x2 %0, %1, %2;"     : "=l"(d) : "l"(a), "l"(b))
#define PACK2(d, lo, hi) asm("mov.b64 %0, {%1, %2};"        : "=l"(d) : "f"(lo), "f"(hi))
#define UNPACK2(lo, hi, s) asm("mov.b64 {%0, %1}, %2;"      : "=f"(lo), "=f"(hi) : "l"(s))

#define CVT_TF32(u, f) asm("cvt.rna.tf32.f32 %0, %1;" : "=r"(u) : "f"(f))

// mma.sync m16n8k8 tf32: C(16x8,f32) += A(16x8,tf32) * B(8x8,tf32)
// A row-major frag: a0=(g,q) a1=(g+8,q) a2=(g,q+4) a3=(g+8,q+4); g=lane>>2, q=lane&3
// B col-major frag: b0=(k=q, n=g) b1=(k=q+4, n=g)
// C frag: c0=(g,2q) c1=(g,2q+1) c2=(g+8,2q) c3=(g+8,2q+1)
__device__ __forceinline__ void mma_tf32(float* c, const uint* a, uint b0, uint b1) {
    asm volatile("mma.sync.aligned.m16n8k8.row.col.f32.tf32.tf32.f32 "
        "{%0,%1,%2,%3}, {%4,%5,%6,%7}, {%8,%9}, {%0,%1,%2,%3};"
        : "+f"(c[0]), "+f"(c[1]), "+f"(c[2]), "+f"(c[3])
        : "r"(a[0]), "r"(a[1]), "r"(a[2]), "r"(a[3]), "r"(b0), "r"(b1));
}

// Scratch: q,k,v in [B,H,S,HD] (tf32-valued fp32 bits; q pre-scaled); att in [B,S,E]
__device__ float g_q[BB*HH*SS*HD];
__device__ float g_k[BB*HH*SS*HD];
__device__ float g_v[BB*HH*SS*HD];
__device__ float g_att[BB*SS*EE];

// ---------------------------------------------------------------------------
// Kernel 1: fused QKV projection via tf32 mma, one head per block.
// grid = (32 token-tiles, 16 heads), 256 threads (8 warps x 16 rows).
// SMEM pitch 76: bank (12g+qd)&31 — conflict-free A and B fragment loads.
// Outputs stored as tf32 bit patterns (q pre-scaled by 1/sqrt(HD)).
// ---------------------------------------------------------------------------
#define XP 76
__global__ void __launch_bounds__(256) qkv_kernel(
    const float* __restrict__ x,
    const float* __restrict__ Wq, const float* __restrict__ bq,
    const float* __restrict__ Wk, const float* __restrict__ bk,
    const float* __restrict__ Wv, const float* __restrict__ bv)
{
    extern __shared__ float sm[];
    uint* sX = (uint*)sm;                        // [128 tok][64] pitch 76
    uint* sW = sX + 128 * XP;                    // 3 x [64 out][64 in] pitch 76
    float* sBias = (float*)(sW + 3 * 64 * XP);   // 3 x 64

    const int tid  = threadIdx.x;
    const int warp = tid >> 5;
    const int lane = tid & 31;
    const int g  = lane >> 2;
    const int qd = lane & 3;
    const int tt = blockIdx.x;
    const int h  = blockIdx.y;

    // Stage x slice [128 tokens][64 dims of head h], tf32
    for (int i = tid; i < 128 * 16; i += 256) {
        const int r = i >> 4, c4 = (i & 15) * 4;
        float4 v = *(const float4*)(x + (long)(tt * 128 + r) * EE + h * 64 + c4);
        uint u0, u1, u2, u3;
        CVT_TF32(u0, v.x); CVT_TF32(u1, v.y);
        CVT_TF32(u2, v.z); CVT_TF32(u3, v.w);
        *(uint4*)(sX + r * XP + c4) = make_uint4(u0, u1, u2, u3);
    }
    // Stage weights (row-major [out][in]), tf32
    {
        const float* Ws[3] = {Wq, Wk, Wv};
        #pragma unroll
        for (int m = 0; m < 3; ++m) {
            for (int i = tid; i < 64 * 16; i += 256) {
                const int r = i >> 4, c4 = (i & 15) * 4;
                float4 v = *(const float4*)(Ws[m] + r * 64 + c4);
                uint u0, u1, u2, u3;
                CVT_TF32(u0, v.x); CVT_TF32(u1, v.y);
                CVT_TF32(u2, v.z); CVT_TF32(u3, v.w);
                *(uint4*)(sW + (m * 64 + r) * XP + c4) = make_uint4(u0, u1, u2, u3);
            }
        }
    }
    if (tid < 64) {
        sBias[tid]       = bq[tid];
        sBias[64 + tid]  = bk[tid];
        sBias[128 + tid] = bv[tid];
    }
    __syncthreads();

    float acc[3][8][4];
    #pragma unroll
    for (int m = 0; m < 3; ++m)
        #pragma unroll
        for (int j = 0; j < 8; ++j)
            #pragma unroll
            for (int r = 0; r < 4; ++r) acc[m][j][r] = 0.f;

    const int r0w = warp * 16;

    #pragma unroll
    for (int t = 0; t < 8; ++t) {
        uint af[4];
        af[0] = sX[(r0w + g)     * XP + 8 * t + qd];
        af[1] = sX[(r0w + g + 8) * XP + 8 * t + qd];
        af[2] = sX[(r0w + g)     * XP + 8 * t + qd + 4];
        af[3] = sX[(r0w + g + 8) * XP + 8 * t + qd + 4];
        #pragma unroll
        for (int m = 0; m < 3; ++m) {
            const uint* sWm = sW + m * 64 * XP;
            #pragma unroll
            for (int j = 0; j < 8; ++j) {
                const uint b0 = sWm[(8 * j + g) * XP + 8 * t + qd];
                const uint b1 = sWm[(8 * j + g) * XP + 8 * t + qd + 4];
                mma_tf32(acc[m][j], af, b0, b1);
            }
        }
    }

    // Epilogue: add bias, (scale q), convert tf32, store
    const int tok = tt * 128 + r0w + g;
    const int b = tok >> 11, s = tok & 2047;     // 128-tiles never straddle batch
    const long base0 = ((long)(b * HH + h) * SS + s) * HD;
    const long base1 = base0 + 8 * HD;
    uint* outs[3] = {(uint*)g_q, (uint*)g_k, (uint*)g_v};
    #pragma unroll
    for (int m = 0; m < 3; ++m) {
        const float scl = (m == 0) ? SCALE : 1.0f;
        #pragma unroll
        for (int j = 0; j < 8; ++j) {
            const int col = 8 * j + 2 * qd;
            const float b0f = sBias[m * 64 + col];
            const float b1f = sBias[m * 64 + col + 1];
            uint u0, u1;
            CVT_TF32(u0, (acc[m][j][0] + b0f) * scl);
            CVT_TF32(u1, (acc[m][j][1] + b1f) * scl);
            *(uint2*)(outs[m] + base0 + col) = make_uint2(u0, u1);
            CVT_TF32(u0, (acc[m][j][2] + b0f) * scl);
            CVT_TF32(u1, (acc[m][j][3] + b1f) * scl);
            *(uint2*)(outs[m] + base1 + col) = make_uint2(u0, u1);
        }
    }
}

// ---------------------------------------------------------------------------
// Kernel 2: causal flash attention via mma.sync tf32 (m16n8k8).
// BR=128 (8 warps x 16 rows), BC=64. Q in registers, K/V/P in SMEM pitch 72.
// Register-staged K/V prefetch. Staging is now pure copies (q/k/v already
// tf32-valued; q pre-scaled in qkv kernel).
// ---------------------------------------------------------------------------
#define PT 72
__global__ void __launch_bounds__(256) attn_kernel()
{
    extern __shared__ float sm[];
    float* sK  = sm;                  // [64 keys][64 d]  pitch 72
    float* sV  = sK + 64 * PT;
    float* sPQ = sV + 64 * PT;        // [128 rows][64]   pitch 72 (Q staging, then P)
    uint* sKu  = (uint*)sK;
    uint* sVu  = (uint*)sV;
    uint* sPQu = (uint*)sPQ;

    const int tid  = threadIdx.x;
    const int warp = tid >> 5;
    const int lane = tid & 31;
    const int g = lane >> 2;
    const int qd = lane & 3;

    const int qb = (int)(gridDim.x - 1 - blockIdx.x);   // big blocks first
    const int h  = blockIdx.y;
    const int b  = blockIdx.z;

    const long head_off = (long)(b * HH + h) * SS * HD;
    const float* Qg = g_q + head_off;
    const float* Kg = g_k + head_off;
    const float* Vg = g_v + head_off;

    const int q0  = qb * 128;
    const int r0w = warp * 16;

    // Prefetch K/V tile kb=0 into registers
    float4 kreg[4], vreg[4];
    #pragma unroll
    for (int u = 0; u < 4; ++u) {
        const int i  = tid + u * 256;
        const int r  = i >> 4;
        const int c4 = (i & 15) * 4;
        kreg[u] = *(const float4*)(Kg + (long)r * HD + c4);
        vreg[u] = *(const float4*)(Vg + (long)r * HD + c4);
    }

    // Stage Q into sPQ (pure copy — already scaled + tf32)
    for (int i = tid; i < 128 * 16; i += 256) {
        const int r  = i >> 4;
        const int c4 = (i & 15) * 4;
        *(float4*)(sPQ + r * PT + c4) = *(const float4*)(Qg + (long)(q0 + r) * HD + c4);
    }
    __syncthreads();

    uint qf[8][4];
    #pragma unroll
    for (int t = 0; t < 8; ++t) {
        qf[t][0] = sPQu[(r0w + g)     * PT + 8 * t + qd];
        qf[t][1] = sPQu[(r0w + g + 8) * PT + 8 * t + qd];
        qf[t][2] = sPQu[(r0w + g)     * PT + 8 * t + qd + 4];
        qf[t][3] = sPQu[(r0w + g + 8) * PT + 8 * t + qd + 4];
    }
    __syncthreads();   // everyone done reading Q from sPQ before it becomes P

    float o[8][4];
    #pragma unroll
    for (int j = 0; j < 8; ++j)
        #pragma unroll
        for (int r = 0; r < 4; ++r) o[j][r] = 0.f;
    float m0 = -INFINITY, m1 = -INFINITY, l0 = 0.f, l1 = 0.f;

    const int kbmax = 2 * qb + 1;
    for (int kb = 0; kb <= kbmax; ++kb) {
        // Store prefetched tile into SMEM (raw copy)
        #pragma unroll
        for (int u = 0; u < 4; ++u) {
            const int i  = tid + u * 256;
            const int r  = i >> 4;
            const int c4 = (i & 15) * 4;
            *(float4*)(sK + r * PT + c4) = kreg[u];
            *(float4*)(sV + r * PT + c4) = vreg[u];
        }
        __syncthreads();

        // Issue next tile's loads now; they complete during compute
        if (kb < kbmax) {
            const int kn = (kb + 1) * 64;
            #pragma unroll
            for (int u = 0; u < 4; ++u) {
                const int i  = tid + u * 256;
                const int r  = i >> 4;
                const int c4 = (i & 15) * 4;
                kreg[u] = *(const float4*)(Kg + (long)(kn + r) * HD + c4);
                vreg[u] = *(const float4*)(Vg + (long)(kn + r) * HD + c4);
            }
        }

        const int k0 = kb * 64;

        // --- S = Q @ K^T ---
        float sc[8][4];
        #pragma unroll
        for (int j = 0; j < 8; ++j)
            #pragma unroll
            for (int r = 0; r < 4; ++r) sc[j][r] = 0.f;

        #pragma unroll
        for (int t = 0; t < 8; ++t) {
            #pragma unroll
            for (int j = 0; j < 8; ++j) {
                const uint b0 = sKu[(8 * j + g) * PT + 8 * t + qd];
                const uint b1 = sKu[(8 * j + g) * PT + 8 * t + qd + 4];
                mma_tf32(sc[j], qf[t], b0, b1);
            }
        }

        // Causal mask
        if (kb >= 2 * qb) {
            const int row0 = q0 + r0w + g;
            const int row1 = row0 + 8;
            #pragma unroll
            for (int j = 0; j < 8; ++j) {
                const int c0 = k0 + 8 * j + 2 * qd;
                if (c0     > row0) sc[j][0] = -1e20f;
                if (c0 + 1 > row0) sc[j][1] = -1e20f;
                if (c0     > row1) sc[j][2] = -1e20f;
                if (c0 + 1 > row1) sc[j][3] = -1e20f;
            }
        }

        // --- Online softmax ---
        float mx0 = -INFINITY, mx1 = -INFINITY;
        #pragma unroll
        for (int j = 0; j < 8; ++j) {
            mx0 = fmaxf(mx0, fmaxf(sc[j][0], sc[j][1]));
            mx1 = fmaxf(mx1, fmaxf(sc[j][2], sc[j][3]));
        }
        mx0 = fmaxf(mx0, __shfl_xor_sync(0xffffffffu, mx0, 1));
        mx0 = fmaxf(mx0, __shfl_xor_sync(0xffffffffu, mx0, 2));
        mx1 = fmaxf(mx1, __shfl_xor_sync(0xffffffffu, mx1, 1));
        mx1 = fmaxf(mx1, __shfl_xor_sync(0xffffffffu, mx1, 2));

        const float mn0 = fmaxf(m0, mx0);
        const float mn1 = fmaxf(m1, mx1);
        const float a0 = __expf(m0 - mn0);
        const float a1 = __expf(m1 - mn1);
        float rs0 = 0.f, rs1 = 0.f;
        #pragma unroll
        for (int j = 0; j < 8; ++j) {
            sc[j][0] = __expf(sc[j][0] - mn0);
            sc[j][1] = __expf(sc[j][1] - mn0);
            sc[j][2] = __expf(sc[j][2] - mn1);
            sc[j][3] = __expf(sc[j][3] - mn1);
            rs0 += sc[j][0] + sc[j][1];
            rs1 += sc[j][2] + sc[j][3];
        }
        rs0 += __shfl_xor_sync(0xffffffffu, rs0, 1);
        rs0 += __shfl_xor_sync(0xffffffffu, rs0, 2);
        rs1 += __shfl_xor_sync(0xffffffffu, rs1, 1);
        rs1 += __shfl_xor_sync(0xffffffffu, rs1, 2);
        l0 = l0 * a0 + rs0;  m0 = mn0;
        l1 = l1 * a1 + rs1;  m1 = mn1;

        // P -> warp-private SMEM rows (tf32); rescale O
        #pragma unroll
        for (int j = 0; j < 8; ++j) {
            uint p0, p1, p2, p3;
            CVT_TF32(p0, sc[j][0]); CVT_TF32(p1, sc[j][1]);
            CVT_TF32(p2, sc[j][2]); CVT_TF32(p3, sc[j][3]);
            *(uint2*)(sPQu + (r0w + g)     * PT + 8 * j + 2 * qd) = make_uint2(p0, p1);
            *(uint2*)(sPQu + (r0w + g + 8) * PT + 8 * j + 2 * qd) = make_uint2(p2, p3);
            o[j][0] *= a0; o[j][1] *= a0;
            o[j][2] *= a1; o[j][3] *= a1;
        }
        __syncwarp();

        // --- O += P @ V ---
        #pragma unroll
        for (int t = 0; t < 8; ++t) {
            uint af[4];
            af[0] = sPQu[(r0w + g)     * PT + 8 * t + qd];
            af[1] = sPQu[(r0w + g + 8) * PT + 8 * t + qd];
            af[2] = sPQu[(r0w + g)     * PT + 8 * t + qd + 4];
            af[3] = sPQu[(r0w + g + 8) * PT + 8 * t + qd + 4];
            #pragma unroll
            for (int j = 0; j < 8; ++j) {
                const uint b0 = sVu[(8 * t + qd)     * PT + 8 * j + g];
                const uint b1 = sVu[(8 * t + qd + 4) * PT + 8 * j + g];
                mma_tf32(o[j], af, b0, b1);
            }
        }
        __syncthreads();   // protect sK/sV before next iteration's store
    }

    // Finalize: O /= l, write to [B, S, H*HD]
    const float inv0 = 1.0f / l0;
    const float inv1 = 1.0f / l1;
    const long row0 = (long)(b * SS + q0 + r0w + g) * EE + h * 64;
    const long row1 = row0 + 8 * EE;
    #pragma unroll
    for (int j = 0; j < 8; ++j) {
        const int c = 8 * j + 2 * qd;
        *(float2*)(g_att + row0 + c) = make_float2(o[j][0] * inv0, o[j][1] * inv0);
        *(float2*)(g_att + row1 + c) = make_float2(o[j][2] * inv1, o[j][3] * inv1);
    }
}

// ---------------------------------------------------------------------------
// Kernel 3: output projection via tf32 mma (unchanged from R8 win).
// ---------------------------------------------------------------------------
#define PP 36
#define PSTG (128 * PP)
__global__ void __launch_bounds__(256) proj_kernel(
    const float* __restrict__ W, const float* __restrict__ bias,
    float* __restrict__ out)
{
    extern __shared__ float smp[];
    uint* sbuf = (uint*)smp;

    const int tid  = threadIdx.x;
    const int warp = tid >> 5;
    const int lane = tid & 31;
    const int g  = lane >> 2;
    const int qd = lane & 3;

    const int jb = blockIdx.x;
    const int ib = blockIdx.y;
    const int wm = (warp >> 1) * 32;
    const int wn = (warp & 1) * 64;

    float acc[2][8][4];
    #pragma unroll
    for (int mt = 0; mt < 2; ++mt)
        #pragma unroll
        for (int j = 0; j < 8; ++j)
            #pragma unroll
            for (int r = 0; r < 4; ++r) acc[mt][j][r] = 0.f;

    float4 areg[4], wreg[4];
    {
        #pragma unroll
        for (int u = 0; u < 4; ++u) {
            const int i = tid + u * 256;
            const int r = i >> 3, c4 = (i & 7) * 4;
            areg[u] = *(const float4*)(g_att + (long)(ib * 128 + r) * 1024 + c4);
            wreg[u] = *(const float4*)(W     + (long)(jb * 128 + r) * 1024 + c4);
        }
        #pragma unroll
        for (int u = 0; u < 4; ++u) {
            const int i = tid + u * 256;
            const int r = i >> 3, c4 = (i & 7) * 4;
            uint a0, a1, a2, a3;
            CVT_TF32(a0, areg[u].x); CVT_TF32(a1, areg[u].y);
            CVT_TF32(a2, areg[u].z); CVT_TF32(a3, areg[u].w);
            *(uint4*)(sbuf + r * PP + c4) = make_uint4(a0, a1, a2, a3);
            CVT_TF32(a0, wreg[u].x); CVT_TF32(a1, wreg[u].y);
            CVT_TF32(a2, wreg[u].z); CVT_TF32(a3, wreg[u].w);
            *(uint4*)(sbuf + PSTG + r * PP + c4) = make_uint4(a0, a1, a2, a3);
        }
    }
    __syncthreads();

    const int NSTG = 1024 / 32;
    for (int s = 0; s < NSTG; ++s) {
        uint* sA = sbuf + (s & 1) * 2 * PSTG;
        uint* sW = sA + PSTG;

        if (s + 1 < NSTG) {
            const int k0 = (s + 1) * 32;
            #pragma unroll
            for (int u = 0; u < 4; ++u) {
                const int i = tid + u * 256;
                const int r = i >> 3, c4 = (i & 7) * 4;
                areg[u] = *(const float4*)(g_att + (long)(ib * 128 + r) * 1024 + k0 + c4);
                wreg[u] = *(const float4*)(W     + (long)(jb * 128 + r) * 1024 + k0 + c4);
            }
        }

        #pragma unroll
        for (int t = 0; t < 4; ++t) {
            const int kk = t * 8;
            uint af0[4], af1[4];
            af0[0] = sA[(wm + g)      * PP + kk + qd];
            af0[1] = sA[(wm + g + 8)  * PP + kk + qd];
            af0[2] = sA[(wm + g)      * PP + kk + qd + 4];
            af0[3] = sA[(wm + g + 8)  * PP + kk + qd + 4];
            af1[0] = sA[(wm + g + 16) * PP + kk + qd];
            af1[1] = sA[(wm + g + 24) * PP + kk + qd];
            af1[2] = sA[(wm + g + 16) * PP + kk + qd + 4];
            af1[3] = sA[(wm + g + 24) * PP + kk + qd + 4];
            #pragma unroll
            for (int j = 0; j < 8; ++j) {
                const uint b0 = sW[(wn + 8 * j + g) * PP + kk + qd];
                const uint b1 = sW[(wn + 8 * j + g) * PP + kk + qd + 4];
                mma_tf32(acc[0][j], af0, b0, b1);
                mma_tf32(acc[1][j], af1, b0, b1);
            }
        }

        if (s + 1 < NSTG) {
            uint* dA = sbuf + ((s + 1) & 1) * 2 * PSTG;
            uint* dW = dA + PSTG;
            #pragma unroll
            for (int u = 0; u < 4; ++u) {
                const int i = tid + u * 256;
                const int r = i >> 3, c4 = (i & 7) * 4;
                uint a0, a1, a2, a3;
                CVT_TF32(a0, areg[u].x); CVT_TF32(a1, areg[u].y);
                CVT_TF32(a2, areg[u].z); CVT_TF32(a3, areg[u].w);
                *(uint4*)(dA + r * PP + c4) = make_uint4(a0, a1, a2, a3);
                CVT_TF32(a0, wreg[u].x); CVT_TF32(a1, wreg[u].y);
                CVT_TF32(a2, wreg[u].z); CVT_TF32(a3, wreg[u].w);
                *(uint4*)(dW + r * PP + c4) = make_uint4(a0, a1, a2, a3);
            }
        }
        __syncthreads();
    }

    #pragma unroll
    for (int mt = 0; mt < 2; ++mt) {
        const int rbase = ib * 128 + wm + mt * 16;
        #pragma unroll
        for (int j = 0; j < 8; ++j) {
            const int col = jb * 128 + wn + 8 * j + 2 * qd;
            const float b0 = bias[col], b1 = bias[col + 1];
            float* p0 = out + (long)(rbase + g) * 1024 + col;
            float* p1 = out + (long)(rbase + g + 8) * 1024 + col;
            *(float2*)p0 = make_float2(acc[mt][j][0] + b0, acc[mt][j][1] + b1);
            *(float2*)p1 = make_float2(acc[mt][j][2] + b0, acc[mt][j][3] + b1);
        }
    }
}

// ---------------------------------------------------------------------------
extern "C" void kernel_launch(void* const* d_in, const int* in_sizes, int n_in,
                              void* d_out, int out_size)
{
    const float* x   = (const float*)d_in[0];
    const float* Wq  = (const float*)d_in[1];
    const float* bq  = (const float*)d_in[2];
    const float* Wk  = (const float*)d_in[3];
    const float* bk  = (const float*)d_in[4];
    const float* Wv  = (const float*)d_in[5];
    const float* bv  = (const float*)d_in[6];
    const float* pw  = (const float*)d_in[7];
    const float* pb  = (const float*)d_in[8];
    float* out = (float*)d_out;

    const int qkv_smem  = (128 * XP + 3 * 64 * XP) * (int)sizeof(float) + 3 * 64 * (int)sizeof(float); // ~98 KB
    const int attn_smem = (64 * PT + 64 * PT + 128 * PT) * (int)sizeof(float); // 73.7 KB
    const int proj_smem = 4 * PSTG * (int)sizeof(float);                       // 73.7 KB
    cudaFuncSetAttribute(qkv_kernel,  cudaFuncAttributeMaxDynamicSharedMemorySize, qkv_smem);
    cudaFuncSetAttribute(attn_kernel, cudaFuncAttributeMaxDynamicSharedMemorySize, attn_smem);
    cudaFuncSetAttribute(proj_kernel, cudaFuncAttributeMaxDynamicSharedMemorySize, proj_smem);

    qkv_kernel<<<dim3((BB * SS) / 128, HH), 256, qkv_smem>>>(x, Wq, bq, Wk, bk, Wv, bv);
    attn_kernel<<<dim3(SS / 128, HH, BB), 256, attn_smem>>>();
    proj_kernel<<<dim3(EE / 128, (BB * SS) / 128), 256, proj_smem>>>(pw, pb, out);
}